// round 1
// baseline (speedup 1.0000x reference)
#include <cuda_runtime.h>
#include <cstdint>

#define Bsz 2
#define Lq 4096
#define Dm 512
#define Hh 8
#define Ee 64
#define NC 32     // number of chunks
#define CS 128    // chunk size
#define BHn (Bsz*Hh)

// ---------------- scratch (device globals; no allocation allowed) ------------
__device__ float g_loglam[BHn * Lq];
__device__ float g_cum[BHn * Lq];
__device__ float g_q[BHn * Lq * Ee];
__device__ float g_k[BHn * Lq * Ee];
__device__ float g_v[BHn * Lq * Ee];
__device__ float g_S[BHn * NC * Ee * Ee];   // chunk KᵀV sums -> exclusive prefix (in place)
__device__ float g_z[BHn * NC * Ee];        // chunk k sums -> exclusive prefix
__device__ float g_attn[Bsz * Lq * Dm];
__device__ float g_out2[Bsz * Lq * Dm];

// ---------------- K0a: decay logits -> log lambda ---------------------------
__global__ void decay_logits_kernel(const float* __restrict__ x,
                                    const float* __restrict__ dw,
                                    const float* __restrict__ db) {
    int warp = (blockIdx.x * blockDim.x + threadIdx.x) >> 5;   // 0..8191 = b*L+l
    int lane = threadIdx.x & 31;
    const float* xr = x + (size_t)warp * Dm;
    float xv[16];
#pragma unroll
    for (int i = 0; i < 16; i++) xv[i] = xr[lane + 32 * i];
    int b = warp >> 12, l = warp & 4095;
#pragma unroll
    for (int h = 0; h < Hh; h++) {
        float p = 0.f;
        const float* wr = dw + (size_t)h * Dm;
#pragma unroll
        for (int i = 0; i < 16; i++) p += xv[i] * wr[lane + 32 * i];
#pragma unroll
        for (int o = 16; o; o >>= 1) p += __shfl_xor_sync(0xffffffffu, p, o);
        if (lane == 0) {
            float logit = p + db[h];
            float lam = 0.9f + 0.1f / (1.f + expf(-logit));
            lam = fmaxf(lam, 1e-6f);
            g_loglam[((size_t)(b * Hh + h)) * Lq + l] = logf(lam);
        }
    }
}

// ---------------- K0b: inclusive scan of log lambda per (b,h), clip ---------
__global__ void cum_scan_kernel() {
    int bh = blockIdx.x;
    int tid = threadIdx.x;                // 512 threads, 8 elems each
    int lane = tid & 31, w = tid >> 5;
    const float* src = g_loglam + (size_t)bh * Lq + tid * 8;
    float v[8]; float s = 0.f;
#pragma unroll
    for (int j = 0; j < 8; j++) { v[j] = src[j]; s += v[j]; }
    float sc = s;
#pragma unroll
    for (int o = 1; o < 32; o <<= 1) {
        float n = __shfl_up_sync(0xffffffffu, sc, o);
        if (lane >= o) sc += n;
    }
    __shared__ float wt[16];
    if (lane == 31) wt[w] = sc;
    __syncthreads();
    if (tid < 16) {
        float ws = wt[tid];
#pragma unroll
        for (int o = 1; o < 16; o <<= 1) {
            float n = __shfl_up_sync(0xffffu, ws, o);
            if (tid >= o) ws += n;
        }
        wt[tid] = ws;
    }
    __syncthreads();
    float base = ((w > 0) ? wt[w - 1] : 0.f) + sc - s;   // exclusive prefix for thread
    float run = base;
    float* dst = g_cum + (size_t)bh * Lq + tid * 8;
#pragma unroll
    for (int j = 0; j < 8; j++) {
        run += v[j];
        dst[j] = fminf(fmaxf(run, -50.f), 50.f);
    }
}

// ---------------- GEMM: C[m][n] = A[m][:] . W[n][:] + bias ------------------
// EPI=1: qkv epilogue (feature map + decay, scatter to g_q/g_k/g_v)
// EPI=0: plain, A = g_attn, writes g_out2
template <int EPI>
__global__ __launch_bounds__(256, 2) void gemm_kernel(const float* __restrict__ Aarg,
                                                      const float* __restrict__ Bw,
                                                      const float* __restrict__ bias) {
    const int BM = 128, BN = 128, BK = 16, KD = 512;
    __shared__ float As[BK][BM + 4];
    __shared__ float Bs[BK][BN + 4];
    const float* Amat = (EPI == 1) ? Aarg : g_attn;
    int tid = threadIdx.x;
    int m0 = blockIdx.y * BM, n0 = blockIdx.x * BN;
    int tx = tid & 15, ty = tid >> 4;
    float acc[8][8];
#pragma unroll
    for (int i = 0; i < 8; i++)
#pragma unroll
        for (int j = 0; j < 8; j++) acc[i][j] = 0.f;
    int lr = tid >> 2;
    int lc = (tid & 3) * 4;
    for (int k0 = 0; k0 < KD; k0 += BK) {
#pragma unroll
        for (int half = 0; half < 2; half++) {
            int row = lr + half * 64;
            float4 va = *(const float4*)&Amat[(size_t)(m0 + row) * KD + k0 + lc];
            As[lc + 0][row] = va.x; As[lc + 1][row] = va.y;
            As[lc + 2][row] = va.z; As[lc + 3][row] = va.w;
            float4 vb = *(const float4*)&Bw[(size_t)(n0 + row) * KD + k0 + lc];
            Bs[lc + 0][row] = vb.x; Bs[lc + 1][row] = vb.y;
            Bs[lc + 2][row] = vb.z; Bs[lc + 3][row] = vb.w;
        }
        __syncthreads();
#pragma unroll
        for (int kk = 0; kk < BK; kk++) {
            float af[8], bf[8];
            float4 a0 = *(const float4*)&As[kk][ty * 8];
            float4 a1 = *(const float4*)&As[kk][ty * 8 + 4];
            af[0] = a0.x; af[1] = a0.y; af[2] = a0.z; af[3] = a0.w;
            af[4] = a1.x; af[5] = a1.y; af[6] = a1.z; af[7] = a1.w;
            float4 b0 = *(const float4*)&Bs[kk][tx * 8];
            float4 b1 = *(const float4*)&Bs[kk][tx * 8 + 4];
            bf[0] = b0.x; bf[1] = b0.y; bf[2] = b0.z; bf[3] = b0.w;
            bf[4] = b1.x; bf[5] = b1.y; bf[6] = b1.z; bf[7] = b1.w;
#pragma unroll
            for (int i = 0; i < 8; i++)
#pragma unroll
                for (int j = 0; j < 8; j++) acc[i][j] += af[i] * bf[j];
        }
        __syncthreads();
    }
    if (EPI == 0) {
#pragma unroll
        for (int i = 0; i < 8; i++) {
            int mm = m0 + ty * 8 + i;
#pragma unroll
            for (int j = 0; j < 8; j++) {
                int n = n0 + tx * 8 + j;
                g_out2[(size_t)mm * Dm + n] = acc[i][j] + bias[n];
            }
        }
    } else {
        int sec = n0 >> 9;                 // 0:q 1:k 2:v (BN=128 divides 512)
        int nb = (n0 & 511) + tx * 8;      // col within section
        int h = nb >> 6;
        int e = nb & 63;                   // e..e+7 within one head
#pragma unroll
        for (int i = 0; i < 8; i++) {
            int mm = m0 + ty * 8 + i;
            int b = mm >> 12, l = mm & 4095;
            size_t rowoff = ((size_t)(b * Hh + h) * Lq + l) * Ee + e;
            if (sec == 2) {
#pragma unroll
                for (int j = 0; j < 8; j++)
                    g_v[rowoff + j] = acc[i][j] + bias[n0 + tx * 8 + j];
            } else {
                float cum = g_cum[(size_t)(b * Hh + h) * Lq + l];
                float dec = (sec == 0) ? expf(cum) : expf(-cum);
                float mul = (sec == 0) ? 0.125f * dec : dec;   // /sqrt(E)=1/8 for q
                float* dst = (sec == 0) ? g_q : g_k;
#pragma unroll
                for (int j = 0; j < 8; j++) {
                    float u = acc[i][j] + bias[n0 + tx * 8 + j];
                    float fm = (u > 0.f) ? (u + 1.f) : expf(u);   // elu(u)+1
                    dst[rowoff + j] = fm * mul;
                }
            }
        }
    }
}

// ---------------- K2: per-chunk S = KᵀV (64x64), z = Σk ---------------------
__global__ void chunk_sum_kernel() {
    __shared__ float Ks[32][Ee];
    __shared__ float Vs[32][Ee];
    int blk = blockIdx.x;              // bh*NC + c
    int c = blk & (NC - 1);
    int bh = blk >> 5;
    int tid = threadIdx.x;             // 256
    int tx = tid & 15, ty = tid >> 4;
    const float* Kb = g_k + ((size_t)bh * Lq + c * CS) * Ee;
    const float* Vb = g_v + ((size_t)bh * Lq + c * CS) * Ee;
    float acc[4][4];
#pragma unroll
    for (int i = 0; i < 4; i++)
#pragma unroll
        for (int j = 0; j < 4; j++) acc[i][j] = 0.f;
    float zacc[4] = {0.f, 0.f, 0.f, 0.f};
    for (int r0 = 0; r0 < CS; r0 += 32) {
#pragma unroll
        for (int u = 0; u < 2; u++) {
            int idx = tid + u * 256;   // float4 idx 0..511
            ((float4*)Ks)[idx] = ((const float4*)(Kb + r0 * Ee))[idx];
            ((float4*)Vs)[idx] = ((const float4*)(Vb + r0 * Ee))[idx];
        }
        __syncthreads();
#pragma unroll
        for (int r = 0; r < 32; r++) {
            float a[4], bq[4];
#pragma unroll
            for (int i = 0; i < 4; i++) a[i] = Ks[r][ty * 4 + i];
#pragma unroll
            for (int j = 0; j < 4; j++) bq[j] = Vs[r][tx * 4 + j];
#pragma unroll
            for (int i = 0; i < 4; i++) {
                zacc[i] += a[i];
#pragma unroll
                for (int j = 0; j < 4; j++) acc[i][j] += a[i] * bq[j];
            }
        }
        __syncthreads();
    }
    float* Sd = g_S + (size_t)blk * Ee * Ee;
#pragma unroll
    for (int i = 0; i < 4; i++)
#pragma unroll
        for (int j = 0; j < 4; j++) Sd[(ty * 4 + i) * Ee + tx * 4 + j] = acc[i][j];
    if (tx == 0) {
        float* zd = g_z + (size_t)blk * Ee;
#pragma unroll
        for (int i = 0; i < 4; i++) zd[ty * 4 + i] = zacc[i];
    }
}

// ---------------- K3: in-place exclusive prefix over chunks -----------------
__global__ void chunk_prefix_kernel() {
    int bh = blockIdx.x;
    int tid = threadIdx.x;   // 256
    for (int idx = tid; idx < Ee * Ee; idx += 256) {
        float carry = 0.f;
        float* p = g_S + (size_t)bh * NC * Ee * Ee + idx;
        for (int c = 0; c < NC; c++) {
            float t = p[(size_t)c * Ee * Ee];
            p[(size_t)c * Ee * Ee] = carry;
            carry += t;
        }
    }
    if (tid < Ee) {
        float carry = 0.f;
        float* p = g_z + (size_t)bh * NC * Ee + tid;
        for (int c = 0; c < NC; c++) {
            float t = p[c * Ee];
            p[c * Ee] = carry;
            carry += t;
        }
    }
}

// ---------------- K4: chunked causal linear attention -----------------------
__global__ __launch_bounds__(128) void attn_kernel() {
    __shared__ float sh[Ee * Ee + Ee];   // 4160 floats = 16.6 KB (S+z, reused for K/V tiles)
    int blk = blockIdx.x;                // bh*NC + c
    int c = blk & 31;
    int bh = blk >> 5;
    int t = threadIdx.x;                 // 0..127, one row each
    const float* qp = g_q + ((size_t)bh * Lq + c * CS + t) * Ee;
    float q[Ee];
#pragma unroll
    for (int i = 0; i < 16; i++) {
        float4 v4 = ((const float4*)qp)[i];
        q[4 * i] = v4.x; q[4 * i + 1] = v4.y; q[4 * i + 2] = v4.z; q[4 * i + 3] = v4.w;
    }
    // load S_prev (4096) + z_prev (64) into smem
    const float* Sp = g_S + (size_t)blk * Ee * Ee;
#pragma unroll
    for (int u = 0; u < 8; u++) ((float4*)sh)[t + u * 128] = ((const float4*)Sp)[t + u * 128];
    if (t < 16) ((float4*)(sh + Ee * Ee))[t] = ((const float4*)(g_z + (size_t)blk * Ee))[t];
    __syncthreads();

    float num[Ee];
#pragma unroll
    for (int f = 0; f < Ee; f++) num[f] = 0.f;
    float den = 1e-6f;
    // inter-chunk: num += q . S_prev ; den += q . z_prev
#pragma unroll
    for (int e = 0; e < Ee; e++) {
        float qe = q[e];
        den += qe * sh[Ee * Ee + e];
        const float4* srow = (const float4*)(sh + e * Ee);
#pragma unroll
        for (int f4 = 0; f4 < 16; f4++) {
            float4 sv = srow[f4];
            num[4 * f4]     += qe * sv.x;
            num[4 * f4 + 1] += qe * sv.y;
            num[4 * f4 + 2] += qe * sv.z;
            num[4 * f4 + 3] += qe * sv.w;
        }
    }
    __syncthreads();

    const float* Kb = g_k + ((size_t)bh * Lq + c * CS) * Ee;
    const float* Vb = g_v + ((size_t)bh * Lq + c * CS) * Ee;
    for (int s0 = 0; s0 < CS; s0 += 32) {
#pragma unroll
        for (int u = 0; u < 4; u++) {
            int idx = t + u * 128;   // float4 idx 0..511
            ((float4*)sh)[idx] = ((const float4*)(Kb + s0 * Ee))[idx];
            ((float4*)(sh + 2048))[idx] = ((const float4*)(Vb + s0 * Ee))[idx];
        }
        __syncthreads();
        for (int s = 0; s < 32; s++) {
            if (s0 + s <= t) {
                float a = 0.f;
                const float4* krow = (const float4*)(sh + s * Ee);
#pragma unroll
                for (int e4 = 0; e4 < 16; e4++) {
                    float4 kv = krow[e4];
                    a += q[4 * e4] * kv.x + q[4 * e4 + 1] * kv.y
                       + q[4 * e4 + 2] * kv.z + q[4 * e4 + 3] * kv.w;
                }
                den += a;
                const float4* vrow = (const float4*)(sh + 2048 + s * Ee);
#pragma unroll
                for (int f4 = 0; f4 < 16; f4++) {
                    float4 vv = vrow[f4];
                    num[4 * f4]     += a * vv.x;
                    num[4 * f4 + 1] += a * vv.y;
                    num[4 * f4 + 2] += a * vv.z;
                    num[4 * f4 + 3] += a * vv.w;
                }
            }
        }
        __syncthreads();
    }
    float invd = 1.0f / den;
    int b = bh >> 3, h = bh & 7;
    float* op = g_attn + ((size_t)(b * Lq + c * CS + t)) * Dm + h * Ee;
#pragma unroll
    for (int f4 = 0; f4 < 16; f4++)
        ((float4*)op)[f4] = make_float4(num[4 * f4] * invd, num[4 * f4 + 1] * invd,
                                        num[4 * f4 + 2] * invd, num[4 * f4 + 3] * invd);
}

// ---------------- K6: RMSNorm ------------------------------------------------
__global__ void rmsnorm_kernel(const float* __restrict__ scale, float* __restrict__ out) {
    int row = blockIdx.x;
    int tid = threadIdx.x;   // 256
    const float* r = g_out2 + (size_t)row * Dm;
    float v0 = r[tid], v1 = r[tid + 256];
    float ss = v0 * v0 + v1 * v1;
#pragma unroll
    for (int o = 16; o; o >>= 1) ss += __shfl_xor_sync(0xffffffffu, ss, o);
    __shared__ float wsum[8];
    __shared__ float rn_s;
    if ((tid & 31) == 0) wsum[tid >> 5] = ss;
    __syncthreads();
    if (tid == 0) {
        float tt = 0.f;
#pragma unroll
        for (int i = 0; i < 8; i++) tt += wsum[i];
        rn_s = rsqrtf(tt * (1.0f / 512.0f) + 1e-8f);
    }
    __syncthreads();
    float rn = rn_s;
    out[(size_t)row * Dm + tid] = v0 * rn * scale[tid];
    out[(size_t)row * Dm + tid + 256] = v1 * rn * scale[tid + 256];
}

// ---------------- launch -----------------------------------------------------
extern "C" void kernel_launch(void* const* d_in, const int* in_sizes, int n_in,
                              void* d_out, int out_size) {
    const float* x          = (const float*)d_in[0];
    const float* qkv_w      = (const float*)d_in[1];
    const float* qkv_b      = (const float*)d_in[2];
    const float* out_w      = (const float*)d_in[3];
    const float* out_b      = (const float*)d_in[4];
    const float* decay_w    = (const float*)d_in[5];
    const float* decay_b    = (const float*)d_in[6];
    const float* norm_scale = (const float*)d_in[7];
    float* out = (float*)d_out;
    (void)in_sizes; (void)n_in; (void)out_size;

    decay_logits_kernel<<<1024, 256>>>(x, decay_w, decay_b);
    cum_scan_kernel<<<BHn, 512>>>();
    gemm_kernel<1><<<dim3(12, 64), 256>>>(x, qkv_w, qkv_b);
    chunk_sum_kernel<<<BHn * NC, 256>>>();
    chunk_prefix_kernel<<<BHn, 256>>>();
    attn_kernel<<<BHn * NC, 128>>>();
    gemm_kernel<0><<<dim3(4, 64), 256>>>(x /*unused*/, out_w, out_b);
    rmsnorm_kernel<<<Bsz * Lq, 256>>>(norm_scale, out);
}

// round 3
// speedup vs baseline: 1.6638x; 1.6638x over previous
#include <cuda_runtime.h>
#include <cuda_bf16.h>
#include <cstdint>

#define Bsz 2
#define Lq 4096
#define Dm 512
#define Hh 8
#define Ee 64
#define NC 32
#define CS 128
#define BHn (Bsz*Hh)

// ---------------- scratch ----------------------------------------------------
__device__ float g_loglam[BHn * Lq];
__device__ float g_cum[BHn * Lq];
__device__ float g_q[BHn * Lq * Ee];
__device__ float g_k[BHn * Lq * Ee];
__device__ float g_v[BHn * Lq * Ee];
__device__ float g_S[BHn * NC * Ee * Ee];
__device__ float g_z[BHn * NC * Ee];
__device__ float g_attn[Bsz * Lq * Dm];
__device__ float g_out2[Bsz * Lq * Dm];
__device__ __align__(16) __nv_bfloat16 g_xhi[Bsz * Lq * Dm];
__device__ __align__(16) __nv_bfloat16 g_xlo[Bsz * Lq * Dm];
__device__ __align__(16) __nv_bfloat16 g_ahi[Bsz * Lq * Dm];
__device__ __align__(16) __nv_bfloat16 g_alo[Bsz * Lq * Dm];
__device__ __align__(16) __nv_bfloat16 g_wq_hi[3 * Dm * Dm];
__device__ __align__(16) __nv_bfloat16 g_wq_lo[3 * Dm * Dm];
__device__ __align__(16) __nv_bfloat16 g_wo_hi[Dm * Dm];
__device__ __align__(16) __nv_bfloat16 g_wo_lo[Dm * Dm];

// ---------------- low-level helpers (sm_80-era ISA; valid at .target sm_103) -
__device__ __forceinline__ uint32_t smem_u32(const void* p) {
    uint32_t a;
    asm("{ .reg .u64 t; cvta.to.shared.u64 t, %1; cvt.u32.u64 %0, t; }" : "=r"(a) : "l"(p));
    return a;
}
__device__ __forceinline__ void ldsm4(uint32_t* r, uint32_t addr) {
    asm volatile("ldmatrix.sync.aligned.m8n8.x4.shared.b16 {%0,%1,%2,%3}, [%4];"
                 : "=r"(r[0]), "=r"(r[1]), "=r"(r[2]), "=r"(r[3]) : "r"(addr));
}
__device__ __forceinline__ void mma16816(float* d, const uint32_t* a, const uint32_t* b) {
    asm volatile("mma.sync.aligned.m16n8k16.row.col.f32.bf16.bf16.f32 "
                 "{%0,%1,%2,%3}, {%4,%5,%6,%7}, {%8,%9}, {%0,%1,%2,%3};"
                 : "+f"(d[0]), "+f"(d[1]), "+f"(d[2]), "+f"(d[3])
                 : "r"(a[0]), "r"(a[1]), "r"(a[2]), "r"(a[3]), "r"(b[0]), "r"(b[1]));
}
#define CP_ASYNC16(sm, gm) \
    asm volatile("cp.async.cg.shared.global [%0], [%1], 16;" :: "r"(sm), "l"(gm))
#define CP_COMMIT() asm volatile("cp.async.commit_group;" ::: "memory")
#define CP_WAIT(n)  asm volatile("cp.async.wait_group %0;" :: "n"(n) : "memory")

// ---------------- fp32 -> bf16 hi/lo split ----------------------------------
template <int DST>
__global__ void split_kernel(const float* __restrict__ src, int n4) {
    int i = blockIdx.x * blockDim.x + threadIdx.x;
    if (i >= n4) return;
    const float* s = (DST == 3) ? g_attn : src;
    __nv_bfloat16* hi = (DST == 0) ? g_xhi : (DST == 1) ? g_wq_hi : (DST == 2) ? g_wo_hi : g_ahi;
    __nv_bfloat16* lo = (DST == 0) ? g_xlo : (DST == 1) ? g_wq_lo : (DST == 2) ? g_wo_lo : g_alo;
    float4 v = ((const float4*)s)[i];
    __nv_bfloat16 h0 = __float2bfloat16(v.x), h1 = __float2bfloat16(v.y);
    __nv_bfloat16 h2 = __float2bfloat16(v.z), h3 = __float2bfloat16(v.w);
    __nv_bfloat16 l0 = __float2bfloat16(v.x - __bfloat162float(h0));
    __nv_bfloat16 l1 = __float2bfloat16(v.y - __bfloat162float(h1));
    __nv_bfloat16 l2 = __float2bfloat16(v.z - __bfloat162float(h2));
    __nv_bfloat16 l3 = __float2bfloat16(v.w - __bfloat162float(h3));
    __nv_bfloat162 ph0; ph0.x = h0; ph0.y = h1;
    __nv_bfloat162 ph1; ph1.x = h2; ph1.y = h3;
    __nv_bfloat162 pl0; pl0.x = l0; pl0.y = l1;
    __nv_bfloat162 pl1; pl1.x = l2; pl1.y = l3;
    ((__nv_bfloat162*)hi)[2 * i] = ph0; ((__nv_bfloat162*)hi)[2 * i + 1] = ph1;
    ((__nv_bfloat162*)lo)[2 * i] = pl0; ((__nv_bfloat162*)lo)[2 * i + 1] = pl1;
}

// ---------------- K0a: decay logits -> log lambda ---------------------------
__global__ void decay_logits_kernel(const float* __restrict__ x,
                                    const float* __restrict__ dw,
                                    const float* __restrict__ db) {
    int warp = (blockIdx.x * blockDim.x + threadIdx.x) >> 5;
    int lane = threadIdx.x & 31;
    const float* xr = x + (size_t)warp * Dm;
    float xv[16];
#pragma unroll
    for (int i = 0; i < 16; i++) xv[i] = xr[lane + 32 * i];
    int b = warp >> 12, l = warp & 4095;
#pragma unroll
    for (int h = 0; h < Hh; h++) {
        float p = 0.f;
        const float* wr = dw + (size_t)h * Dm;
#pragma unroll
        for (int i = 0; i < 16; i++) p += xv[i] * wr[lane + 32 * i];
#pragma unroll
        for (int o = 16; o; o >>= 1) p += __shfl_xor_sync(0xffffffffu, p, o);
        if (lane == 0) {
            float logit = p + db[h];
            float lam = 0.9f + 0.1f / (1.f + expf(-logit));
            lam = fmaxf(lam, 1e-6f);
            g_loglam[((size_t)(b * Hh + h)) * Lq + l] = logf(lam);
        }
    }
}

// ---------------- K0b: inclusive scan of log lambda per (b,h), clip ---------
__global__ void cum_scan_kernel() {
    int bh = blockIdx.x;
    int tid = threadIdx.x;
    int lane = tid & 31, w = tid >> 5;
    const float* src = g_loglam + (size_t)bh * Lq + tid * 8;
    float v[8]; float s = 0.f;
#pragma unroll
    for (int j = 0; j < 8; j++) { v[j] = src[j]; s += v[j]; }
    float sc = s;
#pragma unroll
    for (int o = 1; o < 32; o <<= 1) {
        float n = __shfl_up_sync(0xffffffffu, sc, o);
        if (lane >= o) sc += n;
    }
    __shared__ float wt[16];
    if (lane == 31) wt[w] = sc;
    __syncthreads();
    if (tid < 16) {
        float ws = wt[tid];
#pragma unroll
        for (int o = 1; o < 16; o <<= 1) {
            float n = __shfl_up_sync(0xffffu, ws, o);
            if (tid >= o) ws += n;
        }
        wt[tid] = ws;
    }
    __syncthreads();
    float base = ((w > 0) ? wt[w - 1] : 0.f) + sc - s;
    float run = base;
    float* dst = g_cum + (size_t)bh * Lq + tid * 8;
#pragma unroll
    for (int j = 0; j < 8; j++) {
        run += v[j];
        dst[j] = fminf(fmaxf(run, -50.f), 50.f);
    }
}

// ---------------- HMMA GEMM: C = A @ W^T (+bias, fused epilogue) ------------
// bf16x3 split: C = Ah·Wh + Ah·Wl + Al·Wh (fp32 accum)
// EPI=1: A = x split, W = qkv_w split; epilogue = feature map + decay scatter
// EPI=0: A = attn split, W = out_w split; epilogue = bias -> g_out2
template <int EPI>
__global__ __launch_bounds__(256, 2) void gemm_mma_kernel(const float* __restrict__ bias) {
    extern __shared__ __align__(16) char dynsmem[];
    constexpr int KD = 512, BK = 32;
    constexpr int LDS = BK + 8;            // padded row (80 B) - conflict-free ldmatrix
    constexpr int MS = 128 * LDS;          // bf16 elems per matrix tile
    // stage layout: [Ah][Al][Wh][Wl], 2 stages
    uint32_t sb0 = smem_u32(dynsmem);

    int tid = threadIdx.x;
    int warp = tid >> 5, lane = tid & 31;
    int warp_m = warp & 3, warp_n = warp >> 2;
    int m0 = blockIdx.y * 128, n0 = blockIdx.x * 128;

    const __nv_bfloat16* Ah = (EPI ? g_xhi : g_ahi) + (size_t)m0 * KD;
    const __nv_bfloat16* Al = (EPI ? g_xlo : g_alo) + (size_t)m0 * KD;
    const __nv_bfloat16* Wh = (EPI ? g_wq_hi : g_wo_hi) + (size_t)n0 * KD;
    const __nv_bfloat16* Wl = (EPI ? g_wq_lo : g_wo_lo) + (size_t)n0 * KD;

    float acc[64];
#pragma unroll
    for (int i = 0; i < 64; i++) acc[i] = 0.f;

    // ---- async stage loader: 4 matrices x 128 rows x (32 bf16 = 4 x 16B) ----
    auto load_stage = [&](int s, int kb) {
        const __nv_bfloat16* srcs[4] = { Ah, Al, Wh, Wl };
#pragma unroll
        for (int mtx = 0; mtx < 4; mtx++) {
#pragma unroll
            for (int it = 0; it < 2; it++) {
                int q = tid + it * 256;            // 0..511
                int row = q >> 2, c16 = q & 3;
                uint32_t dst = sb0 + (uint32_t)(((s * 4 + mtx) * MS + row * LDS + c16 * 8) * 2);
                CP_ASYNC16(dst, srcs[mtx] + (size_t)row * KD + kb * BK + c16 * 8);
            }
        }
        CP_COMMIT();
    };

    load_stage(0, 0);
    for (int kb = 0; kb < KD / BK; kb++) {
        if (kb + 1 < KD / BK) { load_stage((kb + 1) & 1, kb + 1); CP_WAIT(1); }
        else CP_WAIT(0);
        __syncthreads();
        uint32_t st = sb0 + (uint32_t)((kb & 1) * 4 * MS * 2);
#pragma unroll
        for (int ks = 0; ks < 2; ks++) {
            uint32_t afh[2][4], afl[2][4];
#pragma unroll
            for (int im = 0; im < 2; im++) {
                int row = warp_m * 32 + im * 16 + (lane & 7) + ((lane >> 3) & 1) * 8;
                int col = ks * 16 + (lane >> 4) * 8;
                ldsm4(afh[im], st + (uint32_t)((0 * MS + row * LDS + col) * 2));
                ldsm4(afl[im], st + (uint32_t)((1 * MS + row * LDS + col) * 2));
            }
#pragma unroll
            for (int jn2 = 0; jn2 < 4; jn2++) {
                uint32_t bfh[4], bfl[4];
                int rowb = warp_n * 64 + jn2 * 16 + (lane & 7) + (lane >> 4) * 8;
                int colb = ks * 16 + ((lane >> 3) & 1) * 8;
                ldsm4(bfh, st + (uint32_t)((2 * MS + rowb * LDS + colb) * 2));
                ldsm4(bfl, st + (uint32_t)((3 * MS + rowb * LDS + colb) * 2));
#pragma unroll
                for (int im = 0; im < 2; im++) {
#pragma unroll
                    for (int na = 0; na < 2; na++) {
                        float* d = &acc[(im * 8 + jn2 * 2 + na) * 4];
                        mma16816(d, afh[im], bfh + na * 2);
                        mma16816(d, afh[im], bfl + na * 2);
                        mma16816(d, afl[im], bfh + na * 2);
                    }
                }
            }
        }
        __syncthreads();
    }

    // ---- stage C through smem for coalesced fused epilogue ----
    float* Csm = (float*)dynsmem;           // 128 x 132 fp32 = 67.6 KB (reuse)
    {
        int r0 = warp_m * 32 + (lane >> 2);
        int c0 = warp_n * 64 + (lane & 3) * 2;
#pragma unroll
        for (int im = 0; im < 2; im++) {
#pragma unroll
            for (int jn = 0; jn < 8; jn++) {
                float* d = &acc[(im * 8 + jn) * 4];
                int rr = r0 + im * 16, cc = c0 + jn * 8;
                Csm[rr * 132 + cc] = d[0];
                Csm[rr * 132 + cc + 1] = d[1];
                Csm[(rr + 8) * 132 + cc] = d[2];
                Csm[(rr + 8) * 132 + cc + 1] = d[3];
            }
        }
    }
    __syncthreads();

#pragma unroll 4
    for (int it = 0; it < 64; it++) {
        int idx = it * 256 + tid;
        int row = idx >> 7, col = idx & 127;
        float val = Csm[row * 132 + col] + bias[n0 + col];
        int m = m0 + row;
        if (EPI == 0) {
            g_out2[(size_t)m * Dm + n0 + col] = val;
        } else {
            int b = m >> 12, l = m & 4095;
            int n = n0 + col;
            int sec = n >> 9;
            int nn = n & 511;
            int h = nn >> 6, e = nn & 63;
            size_t rowoff = ((size_t)(b * Hh + h) * Lq + l) * Ee + e;
            if (sec == 2) {
                g_v[rowoff] = val;
            } else {
                float cum = g_cum[(size_t)(b * Hh + h) * Lq + l];
                float mul = (sec == 0) ? 0.125f * expf(cum) : expf(-cum);
                float fm = (val > 0.f) ? val + 1.f : expf(val);
                ((sec == 0) ? g_q : g_k)[rowoff] = fm * mul;
            }
        }
    }
}

// ---------------- K2: per-chunk S = KᵀV (64x64), z = Σk ---------------------
__global__ void chunk_sum_kernel() {
    __shared__ float Ks[32][Ee];
    __shared__ float Vs[32][Ee];
    int blk = blockIdx.x;
    int c = blk & (NC - 1);
    int bh = blk >> 5;
    int tid = threadIdx.x;
    int tx = tid & 15, ty = tid >> 4;
    const float* Kb = g_k + ((size_t)bh * Lq + c * CS) * Ee;
    const float* Vb = g_v + ((size_t)bh * Lq + c * CS) * Ee;
    float acc[4][4];
#pragma unroll
    for (int i = 0; i < 4; i++)
#pragma unroll
        for (int j = 0; j < 4; j++) acc[i][j] = 0.f;
    float zacc[4] = {0.f, 0.f, 0.f, 0.f};
    for (int r0 = 0; r0 < CS; r0 += 32) {
#pragma unroll
        for (int u = 0; u < 2; u++) {
            int idx = tid + u * 256;
            ((float4*)Ks)[idx] = ((const float4*)(Kb + r0 * Ee))[idx];
            ((float4*)Vs)[idx] = ((const float4*)(Vb + r0 * Ee))[idx];
        }
        __syncthreads();
#pragma unroll
        for (int r = 0; r < 32; r++) {
            float a[4], bq[4];
#pragma unroll
            for (int i = 0; i < 4; i++) a[i] = Ks[r][ty * 4 + i];
#pragma unroll
            for (int j = 0; j < 4; j++) bq[j] = Vs[r][tx * 4 + j];
#pragma unroll
            for (int i = 0; i < 4; i++) {
                zacc[i] += a[i];
#pragma unroll
                for (int j = 0; j < 4; j++) acc[i][j] += a[i] * bq[j];
            }
        }
        __syncthreads();
    }
    float* Sd = g_S + (size_t)blk * Ee * Ee;
#pragma unroll
    for (int i = 0; i < 4; i++)
#pragma unroll
        for (int j = 0; j < 4; j++) Sd[(ty * 4 + i) * Ee + tx * 4 + j] = acc[i][j];
    if (tx == 0) {
        float* zd = g_z + (size_t)blk * Ee;
#pragma unroll
        for (int i = 0; i < 4; i++) zd[ty * 4 + i] = zacc[i];
    }
}

// ---------------- K3: in-place exclusive prefix over chunks -----------------
__global__ void chunk_prefix_kernel() {
    int bh = blockIdx.x;
    int tid = threadIdx.x;
    for (int idx = tid; idx < Ee * Ee; idx += 256) {
        float carry = 0.f;
        float* p = g_S + (size_t)bh * NC * Ee * Ee + idx;
        for (int c = 0; c < NC; c++) {
            float t = p[(size_t)c * Ee * Ee];
            p[(size_t)c * Ee * Ee] = carry;
            carry += t;
        }
    }
    if (tid < Ee) {
        float carry = 0.f;
        float* p = g_z + (size_t)bh * NC * Ee + tid;
        for (int c = 0; c < NC; c++) {
            float t = p[c * Ee];
            p[c * Ee] = carry;
            carry += t;
        }
    }
}

// ---------------- K4: chunked causal linear attention -----------------------
__global__ __launch_bounds__(128) void attn_kernel() {
    __shared__ float sh[Ee * Ee + Ee];
    int blk = blockIdx.x;
    int c = blk & 31;
    int bh = blk >> 5;
    int t = threadIdx.x;
    const float* qp = g_q + ((size_t)bh * Lq + c * CS + t) * Ee;
    float q[Ee];
#pragma unroll
    for (int i = 0; i < 16; i++) {
        float4 v4 = ((const float4*)qp)[i];
        q[4 * i] = v4.x; q[4 * i + 1] = v4.y; q[4 * i + 2] = v4.z; q[4 * i + 3] = v4.w;
    }
    const float* Sp = g_S + (size_t)blk * Ee * Ee;
#pragma unroll
    for (int u = 0; u < 8; u++) ((float4*)sh)[t + u * 128] = ((const float4*)Sp)[t + u * 128];
    if (t < 16) ((float4*)(sh + Ee * Ee))[t] = ((const float4*)(g_z + (size_t)blk * Ee))[t];
    __syncthreads();

    float num[Ee];
#pragma unroll
    for (int f = 0; f < Ee; f++) num[f] = 0.f;
    float den = 1e-6f;
#pragma unroll
    for (int e = 0; e < Ee; e++) {
        float qe = q[e];
        den += qe * sh[Ee * Ee + e];
        const float4* srow = (const float4*)(sh + e * Ee);
#pragma unroll
        for (int f4 = 0; f4 < 16; f4++) {
            float4 sv = srow[f4];
            num[4 * f4]     += qe * sv.x;
            num[4 * f4 + 1] += qe * sv.y;
            num[4 * f4 + 2] += qe * sv.z;
            num[4 * f4 + 3] += qe * sv.w;
        }
    }
    __syncthreads();

    const float* Kb = g_k + ((size_t)bh * Lq + c * CS) * Ee;
    const float* Vb = g_v + ((size_t)bh * Lq + c * CS) * Ee;
    for (int s0 = 0; s0 < CS; s0 += 32) {
#pragma unroll
        for (int u = 0; u < 4; u++) {
            int idx = t + u * 128;
            ((float4*)sh)[idx] = ((const float4*)(Kb + s0 * Ee))[idx];
            ((float4*)(sh + 2048))[idx] = ((const float4*)(Vb + s0 * Ee))[idx];
        }
        __syncthreads();
        for (int s = 0; s < 32; s++) {
            if (s0 + s <= t) {
                float a = 0.f;
                const float4* krow = (const float4*)(sh + s * Ee);
#pragma unroll
                for (int e4 = 0; e4 < 16; e4++) {
                    float4 kv = krow[e4];
                    a += q[4 * e4] * kv.x + q[4 * e4 + 1] * kv.y
                       + q[4 * e4 + 2] * kv.z + q[4 * e4 + 3] * kv.w;
                }
                den += a;
                const float4* vrow = (const float4*)(sh + 2048 + s * Ee);
#pragma unroll
                for (int f4 = 0; f4 < 16; f4++) {
                    float4 vv = vrow[f4];
                    num[4 * f4]     += a * vv.x;
                    num[4 * f4 + 1] += a * vv.y;
                    num[4 * f4 + 2] += a * vv.z;
                    num[4 * f4 + 3] += a * vv.w;
                }
            }
        }
        __syncthreads();
    }
    float invd = 1.0f / den;
    int b = bh >> 3, h = bh & 7;
    float* op = g_attn + ((size_t)(b * Lq + c * CS + t)) * Dm + h * Ee;
#pragma unroll
    for (int f4 = 0; f4 < 16; f4++)
        ((float4*)op)[f4] = make_float4(num[4 * f4] * invd, num[4 * f4 + 1] * invd,
                                        num[4 * f4 + 2] * invd, num[4 * f4 + 3] * invd);
}

// ---------------- K6: RMSNorm ------------------------------------------------
__global__ void rmsnorm_kernel(const float* __restrict__ scale, float* __restrict__ out) {
    int row = blockIdx.x;
    int tid = threadIdx.x;
    const float* r = g_out2 + (size_t)row * Dm;
    float v0 = r[tid], v1 = r[tid + 256];
    float ss = v0 * v0 + v1 * v1;
#pragma unroll
    for (int o = 16; o; o >>= 1) ss += __shfl_xor_sync(0xffffffffu, ss, o);
    __shared__ float wsum[8];
    __shared__ float rn_s;
    if ((tid & 31) == 0) wsum[tid >> 5] = ss;
    __syncthreads();
    if (tid == 0) {
        float tt = 0.f;
#pragma unroll
        for (int i = 0; i < 8; i++) tt += wsum[i];
        rn_s = rsqrtf(tt * (1.0f / 512.0f) + 1e-8f);
    }
    __syncthreads();
    float rn = rn_s;
    out[(size_t)row * Dm + tid] = v0 * rn * scale[tid];
    out[(size_t)row * Dm + tid + 256] = v1 * rn * scale[tid + 256];
}

// ---------------- launch -----------------------------------------------------
extern "C" void kernel_launch(void* const* d_in, const int* in_sizes, int n_in,
                              void* d_out, int out_size) {
    const float* x          = (const float*)d_in[0];
    const float* qkv_w      = (const float*)d_in[1];
    const float* qkv_b      = (const float*)d_in[2];
    const float* out_w      = (const float*)d_in[3];
    const float* out_b      = (const float*)d_in[4];
    const float* decay_w    = (const float*)d_in[5];
    const float* decay_b    = (const float*)d_in[6];
    const float* norm_scale = (const float*)d_in[7];
    float* out = (float*)d_out;
    (void)in_sizes; (void)n_in; (void)out_size;

    // dynamic smem: max(2 stages x 4 mats x 128 x 40 bf16 = 81920 B, C staging 67584 B)
    const int DYN = 81920;
    static bool attr_set = false;
    if (!attr_set) {
        cudaFuncSetAttribute(gemm_mma_kernel<1>, cudaFuncAttributeMaxDynamicSharedMemorySize, DYN);
        cudaFuncSetAttribute(gemm_mma_kernel<0>, cudaFuncAttributeMaxDynamicSharedMemorySize, DYN);
        attr_set = true;
    }

    split_kernel<0><<<4096, 256>>>(x, (Bsz * Lq * Dm) / 4);
    split_kernel<1><<<768, 256>>>(qkv_w, (3 * Dm * Dm) / 4);
    split_kernel<2><<<256, 256>>>(out_w, (Dm * Dm) / 4);

    decay_logits_kernel<<<1024, 256>>>(x, decay_w, decay_b);
    cum_scan_kernel<<<BHn, 512>>>();

    gemm_mma_kernel<1><<<dim3(12, 64), 256, DYN>>>(qkv_b);

    chunk_sum_kernel<<<BHn * NC, 256>>>();
    chunk_prefix_kernel<<<BHn, 256>>>();
    attn_kernel<<<BHn * NC, 128>>>();

    split_kernel<3><<<4096, 256>>>(nullptr, (Bsz * Lq * Dm) / 4);
    gemm_mma_kernel<0><<<dim3(4, 64), 256, DYN>>>(out_b);

    rmsnorm_kernel<<<Bsz * Lq, 256>>>(norm_scale, out);
}

// round 4
// speedup vs baseline: 1.7858x; 1.0733x over previous
#include <cuda_runtime.h>
#include <cuda_bf16.h>
#include <cstdint>

#define Bsz 2
#define Lq 4096
#define Dm 512
#define Hh 8
#define Ee 64
#define NC 32
#define CS 128
#define BHn (Bsz*Hh)

// ---------------- scratch ----------------------------------------------------
__device__ float g_loglam[BHn * Lq];
__device__ float g_cum[BHn * Lq];
__device__ float g_q[BHn * Lq * Ee];
__device__ float g_k[BHn * Lq * Ee];
__device__ float g_v[BHn * Lq * Ee];
__device__ float g_S[BHn * NC * Ee * Ee];
__device__ float g_z[BHn * NC * Ee];
__device__ float g_out2[Bsz * Lq * Dm];
__device__ __align__(16) __nv_bfloat16 g_xhi[Bsz * Lq * Dm];
__device__ __align__(16) __nv_bfloat16 g_xlo[Bsz * Lq * Dm];
__device__ __align__(16) __nv_bfloat16 g_ahi[Bsz * Lq * Dm];
__device__ __align__(16) __nv_bfloat16 g_alo[Bsz * Lq * Dm];
__device__ __align__(16) __nv_bfloat16 g_wq_hi[3 * Dm * Dm];
__device__ __align__(16) __nv_bfloat16 g_wq_lo[3 * Dm * Dm];
__device__ __align__(16) __nv_bfloat16 g_wo_hi[Dm * Dm];
__device__ __align__(16) __nv_bfloat16 g_wo_lo[Dm * Dm];

// ---------------- low-level helpers -------------------------------------------
__device__ __forceinline__ uint32_t smem_u32(const void* p) {
    uint32_t a;
    asm("{ .reg .u64 t; cvta.to.shared.u64 t, %1; cvt.u32.u64 %0, t; }" : "=r"(a) : "l"(p));
    return a;
}
__device__ __forceinline__ void ldsm4(uint32_t* r, uint32_t addr) {
    asm volatile("ldmatrix.sync.aligned.m8n8.x4.shared.b16 {%0,%1,%2,%3}, [%4];"
                 : "=r"(r[0]), "=r"(r[1]), "=r"(r[2]), "=r"(r[3]) : "r"(addr));
}
__device__ __forceinline__ void mma16816(float* d, const uint32_t* a, const uint32_t* b) {
    asm volatile("mma.sync.aligned.m16n8k16.row.col.f32.bf16.bf16.f32 "
                 "{%0,%1,%2,%3}, {%4,%5,%6,%7}, {%8,%9}, {%0,%1,%2,%3};"
                 : "+f"(d[0]), "+f"(d[1]), "+f"(d[2]), "+f"(d[3])
                 : "r"(a[0]), "r"(a[1]), "r"(a[2]), "r"(a[3]), "r"(b[0]), "r"(b[1]));
}
#define CP_ASYNC16(sm, gm) \
    asm volatile("cp.async.cg.shared.global [%0], [%1], 16;" :: "r"(sm), "l"(gm))
#define CP_COMMIT() asm volatile("cp.async.commit_group;" ::: "memory")
#define CP_WAIT(n)  asm volatile("cp.async.wait_group %0;" :: "n"(n) : "memory")

__device__ __forceinline__ void split2(float v0, float v1,
                                       __nv_bfloat162& ph, __nv_bfloat162& pl) {
    __nv_bfloat16 h0 = __float2bfloat16(v0), h1 = __float2bfloat16(v1);
    ph.x = h0; ph.y = h1;
    pl.x = __float2bfloat16(v0 - __bfloat162float(h0));
    pl.y = __float2bfloat16(v1 - __bfloat162float(h1));
}

// ---------------- K0: fused x split + decay logits (one pass over x) ---------
__global__ __launch_bounds__(256) void split_x_decay_kernel(const float* __restrict__ x,
                                                            const float* __restrict__ dw,
                                                            const float* __restrict__ db) {
    int warp = (blockIdx.x * blockDim.x + threadIdx.x) >> 5;   // 0..8191 row
    int lane = threadIdx.x & 31;
    const float4* xr = (const float4*)(x + (size_t)warp * Dm);
    float4 xv[4];
#pragma unroll
    for (int i = 0; i < 4; i++) xv[i] = xr[lane + 32 * i];
    // split write
    __nv_bfloat162* hi = (__nv_bfloat162*)(g_xhi + (size_t)warp * Dm);
    __nv_bfloat162* lo = (__nv_bfloat162*)(g_xlo + (size_t)warp * Dm);
#pragma unroll
    for (int i = 0; i < 4; i++) {
        int idx = lane + 32 * i;
        __nv_bfloat162 ph0, pl0, ph1, pl1;
        split2(xv[i].x, xv[i].y, ph0, pl0);
        split2(xv[i].z, xv[i].w, ph1, pl1);
        hi[2 * idx] = ph0; hi[2 * idx + 1] = ph1;
        lo[2 * idx] = pl0; lo[2 * idx + 1] = pl1;
    }
    // decay logits
    int b = warp >> 12, l = warp & 4095;
#pragma unroll
    for (int h = 0; h < Hh; h++) {
        const float4* wr = (const float4*)(dw + (size_t)h * Dm);
        float p = 0.f;
#pragma unroll
        for (int i = 0; i < 4; i++) {
            float4 w = wr[lane + 32 * i];
            p += xv[i].x * w.x + xv[i].y * w.y + xv[i].z * w.z + xv[i].w * w.w;
        }
#pragma unroll
        for (int o = 16; o; o >>= 1) p += __shfl_xor_sync(0xffffffffu, p, o);
        if (lane == 0) {
            float logit = p + db[h];
            float lam = 0.9f + 0.1f / (1.f + expf(-logit));
            lam = fmaxf(lam, 1e-6f);
            g_loglam[((size_t)(b * Hh + h)) * Lq + l] = logf(lam);
        }
    }
}

// ---------------- K0w: both weight splits in one launch ----------------------
__global__ void split_w_kernel(const float* __restrict__ qkv_w,
                               const float* __restrict__ out_w) {
    int i = blockIdx.x * blockDim.x + threadIdx.x;   // float4 index
    const int nq = 3 * Dm * Dm / 4;
    const float* s; __nv_bfloat16 *hi, *lo; int j;
    if (i < nq) { s = qkv_w; hi = g_wq_hi; lo = g_wq_lo; j = i; }
    else {
        j = i - nq;
        if (j >= Dm * Dm / 4) return;
        s = out_w; hi = g_wo_hi; lo = g_wo_lo;
    }
    float4 v = ((const float4*)s)[j];
    __nv_bfloat162 ph0, pl0, ph1, pl1;
    split2(v.x, v.y, ph0, pl0);
    split2(v.z, v.w, ph1, pl1);
    ((__nv_bfloat162*)hi)[2 * j] = ph0; ((__nv_bfloat162*)hi)[2 * j + 1] = ph1;
    ((__nv_bfloat162*)lo)[2 * j] = pl0; ((__nv_bfloat162*)lo)[2 * j + 1] = pl1;
}

// ---------------- K0b: inclusive scan of log lambda per (b,h), clip ----------
__global__ void cum_scan_kernel() {
    int bh = blockIdx.x;
    int tid = threadIdx.x;
    int lane = tid & 31, w = tid >> 5;
    const float* src = g_loglam + (size_t)bh * Lq + tid * 8;
    float v[8]; float s = 0.f;
#pragma unroll
    for (int j = 0; j < 8; j++) { v[j] = src[j]; s += v[j]; }
    float sc = s;
#pragma unroll
    for (int o = 1; o < 32; o <<= 1) {
        float n = __shfl_up_sync(0xffffffffu, sc, o);
        if (lane >= o) sc += n;
    }
    __shared__ float wt[16];
    if (lane == 31) wt[w] = sc;
    __syncthreads();
    if (tid < 16) {
        float ws = wt[tid];
#pragma unroll
        for (int o = 1; o < 16; o <<= 1) {
            float n = __shfl_up_sync(0xffffu, ws, o);
            if (tid >= o) ws += n;
        }
        wt[tid] = ws;
    }
    __syncthreads();
    float base = ((w > 0) ? wt[w - 1] : 0.f) + sc - s;
    float run = base;
    float* dst = g_cum + (size_t)bh * Lq + tid * 8;
#pragma unroll
    for (int j = 0; j < 8; j++) {
        run += v[j];
        dst[j] = fminf(fmaxf(run, -50.f), 50.f);
    }
}

// ---------------- HMMA GEMM (bf16x3 split) -----------------------------------
template <int EPI>
__global__ __launch_bounds__(256, 2) void gemm_mma_kernel(const float* __restrict__ bias) {
    extern __shared__ __align__(16) char dynsmem[];
    constexpr int KD = 512, BK = 32;
    constexpr int LDS = BK + 8;
    constexpr int MS = 128 * LDS;
    uint32_t sb0 = smem_u32(dynsmem);

    int tid = threadIdx.x;
    int warp = tid >> 5, lane = tid & 31;
    int warp_m = warp & 3, warp_n = warp >> 2;
    int m0 = blockIdx.y * 128, n0 = blockIdx.x * 128;

    const __nv_bfloat16* Ah = (EPI ? g_xhi : g_ahi) + (size_t)m0 * KD;
    const __nv_bfloat16* Al = (EPI ? g_xlo : g_alo) + (size_t)m0 * KD;
    const __nv_bfloat16* Wh = (EPI ? g_wq_hi : g_wo_hi) + (size_t)n0 * KD;
    const __nv_bfloat16* Wl = (EPI ? g_wq_lo : g_wo_lo) + (size_t)n0 * KD;

    float acc[64];
#pragma unroll
    for (int i = 0; i < 64; i++) acc[i] = 0.f;

    auto load_stage = [&](int s, int kb) {
        const __nv_bfloat16* srcs[4] = { Ah, Al, Wh, Wl };
#pragma unroll
        for (int mtx = 0; mtx < 4; mtx++) {
#pragma unroll
            for (int it = 0; it < 2; it++) {
                int q = tid + it * 256;
                int row = q >> 2, c16 = q & 3;
                uint32_t dst = sb0 + (uint32_t)(((s * 4 + mtx) * MS + row * LDS + c16 * 8) * 2);
                CP_ASYNC16(dst, srcs[mtx] + (size_t)row * KD + kb * BK + c16 * 8);
            }
        }
        CP_COMMIT();
    };

    load_stage(0, 0);
    for (int kb = 0; kb < KD / BK; kb++) {
        if (kb + 1 < KD / BK) { load_stage((kb + 1) & 1, kb + 1); CP_WAIT(1); }
        else CP_WAIT(0);
        __syncthreads();
        uint32_t st = sb0 + (uint32_t)((kb & 1) * 4 * MS * 2);
#pragma unroll
        for (int ks = 0; ks < 2; ks++) {
            uint32_t afh[2][4], afl[2][4];
#pragma unroll
            for (int im = 0; im < 2; im++) {
                int row = warp_m * 32 + im * 16 + (lane & 7) + ((lane >> 3) & 1) * 8;
                int col = ks * 16 + (lane >> 4) * 8;
                ldsm4(afh[im], st + (uint32_t)((0 * MS + row * LDS + col) * 2));
                ldsm4(afl[im], st + (uint32_t)((1 * MS + row * LDS + col) * 2));
            }
#pragma unroll
            for (int jn2 = 0; jn2 < 4; jn2++) {
                uint32_t bfh[4], bfl[4];
                int rowb = warp_n * 64 + jn2 * 16 + (lane & 7) + (lane >> 4) * 8;
                int colb = ks * 16 + ((lane >> 3) & 1) * 8;
                ldsm4(bfh, st + (uint32_t)((2 * MS + rowb * LDS + colb) * 2));
                ldsm4(bfl, st + (uint32_t)((3 * MS + rowb * LDS + colb) * 2));
#pragma unroll
                for (int im = 0; im < 2; im++) {
#pragma unroll
                    for (int na = 0; na < 2; na++) {
                        float* d = &acc[(im * 8 + jn2 * 2 + na) * 4];
                        mma16816(d, afh[im], bfh + na * 2);
                        mma16816(d, afh[im], bfl + na * 2);
                        mma16816(d, afl[im], bfh + na * 2);
                    }
                }
            }
        }
        __syncthreads();
    }

    float* Csm = (float*)dynsmem;
    {
        int r0 = warp_m * 32 + (lane >> 2);
        int c0 = warp_n * 64 + (lane & 3) * 2;
#pragma unroll
        for (int im = 0; im < 2; im++) {
#pragma unroll
            for (int jn = 0; jn < 8; jn++) {
                float* d = &acc[(im * 8 + jn) * 4];
                int rr = r0 + im * 16, cc = c0 + jn * 8;
                Csm[rr * 132 + cc] = d[0];
                Csm[rr * 132 + cc + 1] = d[1];
                Csm[(rr + 8) * 132 + cc] = d[2];
                Csm[(rr + 8) * 132 + cc + 1] = d[3];
            }
        }
    }
    __syncthreads();

#pragma unroll 4
    for (int it = 0; it < 64; it++) {
        int idx = it * 256 + tid;
        int row = idx >> 7, col = idx & 127;
        float val = Csm[row * 132 + col] + bias[n0 + col];
        int m = m0 + row;
        if (EPI == 0) {
            g_out2[(size_t)m * Dm + n0 + col] = val;
        } else {
            int b = m >> 12, l = m & 4095;
            int n = n0 + col;
            int sec = n >> 9;
            int nn = n & 511;
            int h = nn >> 6, e = nn & 63;
            size_t rowoff = ((size_t)(b * Hh + h) * Lq + l) * Ee + e;
            if (sec == 2) {
                g_v[rowoff] = val;
            } else {
                float cum = g_cum[(size_t)(b * Hh + h) * Lq + l];
                float mul = (sec == 0) ? 0.125f * expf(cum) : expf(-cum);
                float fm = (val > 0.f) ? val + 1.f : expf(val);
                ((sec == 0) ? g_q : g_k)[rowoff] = fm * mul;
            }
        }
    }
}

// ---------------- K2: per-chunk S = KᵀV (64x64), z = Σk ----------------------
__global__ void chunk_sum_kernel() {
    __shared__ float Ks[32][Ee];
    __shared__ float Vs[32][Ee];
    int blk = blockIdx.x;
    int c = blk & (NC - 1);
    int bh = blk >> 5;
    int tid = threadIdx.x;
    int tx = tid & 15, ty = tid >> 4;
    const float* Kb = g_k + ((size_t)bh * Lq + c * CS) * Ee;
    const float* Vb = g_v + ((size_t)bh * Lq + c * CS) * Ee;
    float acc[4][4];
#pragma unroll
    for (int i = 0; i < 4; i++)
#pragma unroll
        for (int j = 0; j < 4; j++) acc[i][j] = 0.f;
    float zacc[4] = {0.f, 0.f, 0.f, 0.f};
    for (int r0 = 0; r0 < CS; r0 += 32) {
#pragma unroll
        for (int u = 0; u < 2; u++) {
            int idx = tid + u * 256;
            ((float4*)Ks)[idx] = ((const float4*)(Kb + r0 * Ee))[idx];
            ((float4*)Vs)[idx] = ((const float4*)(Vb + r0 * Ee))[idx];
        }
        __syncthreads();
#pragma unroll
        for (int r = 0; r < 32; r++) {
            float a[4], bq[4];
#pragma unroll
            for (int i = 0; i < 4; i++) a[i] = Ks[r][ty * 4 + i];
#pragma unroll
            for (int j = 0; j < 4; j++) bq[j] = Vs[r][tx * 4 + j];
#pragma unroll
            for (int i = 0; i < 4; i++) {
                zacc[i] += a[i];
#pragma unroll
                for (int j = 0; j < 4; j++) acc[i][j] += a[i] * bq[j];
            }
        }
        __syncthreads();
    }
    float* Sd = g_S + (size_t)blk * Ee * Ee;
#pragma unroll
    for (int i = 0; i < 4; i++)
#pragma unroll
        for (int j = 0; j < 4; j++) Sd[(ty * 4 + i) * Ee + tx * 4 + j] = acc[i][j];
    if (tx == 0) {
        float* zd = g_z + (size_t)blk * Ee;
#pragma unroll
        for (int i = 0; i < 4; i++) zd[ty * 4 + i] = zacc[i];
    }
}

// ---------------- K3: exclusive prefix over chunks (full-width grid) ---------
__global__ __launch_bounds__(512) void chunk_prefix_kernel() {
    int bh = blockIdx.x;
    int idx = blockIdx.y * 512 + threadIdx.x;   // 0..4095 (e,f) column
    float* p = g_S + (size_t)bh * NC * (Ee * Ee) + idx;
    float v[NC];
#pragma unroll
    for (int c = 0; c < NC; c++) v[c] = p[(size_t)c * (Ee * Ee)];
    float carry = 0.f;
#pragma unroll
    for (int c = 0; c < NC; c++) { p[(size_t)c * (Ee * Ee)] = carry; carry += v[c]; }
    if (blockIdx.y == 0 && threadIdx.x < Ee) {
        float* pz = g_z + (size_t)bh * NC * Ee + threadIdx.x;
        float zv[NC];
#pragma unroll
        for (int c = 0; c < NC; c++) zv[c] = pz[c * Ee];
        float zc = 0.f;
#pragma unroll
        for (int c = 0; c < NC; c++) { pz[c * Ee] = zc; zc += zv[c]; }
    }
}

// ---------------- K4: chunked causal linear attention (writes bf16 split) ----
__global__ __launch_bounds__(128) void attn_kernel() {
    __shared__ float sh[Ee * Ee + Ee];
    int blk = blockIdx.x;
    int c = blk & 31;
    int bh = blk >> 5;
    int t = threadIdx.x;
    const float* qp = g_q + ((size_t)bh * Lq + c * CS + t) * Ee;
    float q[Ee];
#pragma unroll
    for (int i = 0; i < 16; i++) {
        float4 v4 = ((const float4*)qp)[i];
        q[4 * i] = v4.x; q[4 * i + 1] = v4.y; q[4 * i + 2] = v4.z; q[4 * i + 3] = v4.w;
    }
    const float* Sp = g_S + (size_t)blk * Ee * Ee;
#pragma unroll
    for (int u = 0; u < 8; u++) ((float4*)sh)[t + u * 128] = ((const float4*)Sp)[t + u * 128];
    if (t < 16) ((float4*)(sh + Ee * Ee))[t] = ((const float4*)(g_z + (size_t)blk * Ee))[t];
    __syncthreads();

    float num[Ee];
#pragma unroll
    for (int f = 0; f < Ee; f++) num[f] = 0.f;
    float den = 1e-6f;
#pragma unroll
    for (int e = 0; e < Ee; e++) {
        float qe = q[e];
        den += qe * sh[Ee * Ee + e];
        const float4* srow = (const float4*)(sh + e * Ee);
#pragma unroll
        for (int f4 = 0; f4 < 16; f4++) {
            float4 sv = srow[f4];
            num[4 * f4]     += qe * sv.x;
            num[4 * f4 + 1] += qe * sv.y;
            num[4 * f4 + 2] += qe * sv.z;
            num[4 * f4 + 3] += qe * sv.w;
        }
    }
    __syncthreads();

    const float* Kb = g_k + ((size_t)bh * Lq + c * CS) * Ee;
    const float* Vb = g_v + ((size_t)bh * Lq + c * CS) * Ee;
    for (int s0 = 0; s0 < CS; s0 += 32) {
#pragma unroll
        for (int u = 0; u < 4; u++) {
            int idx = t + u * 128;
            ((float4*)sh)[idx] = ((const float4*)(Kb + s0 * Ee))[idx];
            ((float4*)(sh + 2048))[idx] = ((const float4*)(Vb + s0 * Ee))[idx];
        }
        __syncthreads();
        for (int s = 0; s < 32; s++) {
            if (s0 + s <= t) {
                float a = 0.f;
                const float4* krow = (const float4*)(sh + s * Ee);
#pragma unroll
                for (int e4 = 0; e4 < 16; e4++) {
                    float4 kv = krow[e4];
                    a += q[4 * e4] * kv.x + q[4 * e4 + 1] * kv.y
                       + q[4 * e4 + 2] * kv.z + q[4 * e4 + 3] * kv.w;
                }
                den += a;
                const float4* vrow = (const float4*)(sh + 2048 + s * Ee);
#pragma unroll
                for (int f4 = 0; f4 < 16; f4++) {
                    float4 vv = vrow[f4];
                    num[4 * f4]     += a * vv.x;
                    num[4 * f4 + 1] += a * vv.y;
                    num[4 * f4 + 2] += a * vv.z;
                    num[4 * f4 + 3] += a * vv.w;
                }
            }
        }
        __syncthreads();
    }
    float invd = 1.0f / den;
    int b = bh >> 3, h = bh & 7;
    size_t off = ((size_t)(b * Lq + c * CS + t)) * Dm + h * Ee;
    __nv_bfloat162* oh = (__nv_bfloat162*)(g_ahi + off);
    __nv_bfloat162* ol = (__nv_bfloat162*)(g_alo + off);
#pragma unroll
    for (int f2 = 0; f2 < 32; f2++) {
        float v0 = num[2 * f2] * invd, v1 = num[2 * f2 + 1] * invd;
        __nv_bfloat162 ph, pl;
        split2(v0, v1, ph, pl);
        oh[f2] = ph; ol[f2] = pl;
    }
}

// ---------------- K6: RMSNorm -------------------------------------------------
__global__ void rmsnorm_kernel(const float* __restrict__ scale, float* __restrict__ out) {
    int row = blockIdx.x;
    int tid = threadIdx.x;
    const float* r = g_out2 + (size_t)row * Dm;
    float v0 = r[tid], v1 = r[tid + 256];
    float ss = v0 * v0 + v1 * v1;
#pragma unroll
    for (int o = 16; o; o >>= 1) ss += __shfl_xor_sync(0xffffffffu, ss, o);
    __shared__ float wsum[8];
    __shared__ float rn_s;
    if ((tid & 31) == 0) wsum[tid >> 5] = ss;
    __syncthreads();
    if (tid == 0) {
        float tt = 0.f;
#pragma unroll
        for (int i = 0; i < 8; i++) tt += wsum[i];
        rn_s = rsqrtf(tt * (1.0f / 512.0f) + 1e-8f);
    }
    __syncthreads();
    float rn = rn_s;
    out[(size_t)row * Dm + tid] = v0 * rn * scale[tid];
    out[(size_t)row * Dm + tid + 256] = v1 * rn * scale[tid + 256];
}

// ---------------- launch ------------------------------------------------------
extern "C" void kernel_launch(void* const* d_in, const int* in_sizes, int n_in,
                              void* d_out, int out_size) {
    const float* x          = (const float*)d_in[0];
    const float* qkv_w      = (const float*)d_in[1];
    const float* qkv_b      = (const float*)d_in[2];
    const float* out_w      = (const float*)d_in[3];
    const float* out_b      = (const float*)d_in[4];
    const float* decay_w    = (const float*)d_in[5];
    const float* decay_b    = (const float*)d_in[6];
    const float* norm_scale = (const float*)d_in[7];
    float* out = (float*)d_out;
    (void)in_sizes; (void)n_in; (void)out_size;

    const int DYN = 81920;
    static bool attr_set = false;
    if (!attr_set) {
        cudaFuncSetAttribute(gemm_mma_kernel<1>, cudaFuncAttributeMaxDynamicSharedMemorySize, DYN);
        cudaFuncSetAttribute(gemm_mma_kernel<0>, cudaFuncAttributeMaxDynamicSharedMemorySize, DYN);
        attr_set = true;
    }

    split_w_kernel<<<1024, 256>>>(qkv_w, out_w);
    split_x_decay_kernel<<<1024, 256>>>(x, decay_w, decay_b);
    cum_scan_kernel<<<BHn, 512>>>();

    gemm_mma_kernel<1><<<dim3(12, 64), 256, DYN>>>(qkv_b);

    chunk_sum_kernel<<<BHn * NC, 256>>>();
    chunk_prefix_kernel<<<dim3(BHn, 8), 512>>>();
    attn_kernel<<<BHn * NC, 128>>>();

    gemm_mma_kernel<0><<<dim3(4, 64), 256, DYN>>>(out_b);

    rmsnorm_kernel<<<Bsz * Lq, 256>>>(norm_scale, out);
}

// round 5
// speedup vs baseline: 1.9005x; 1.0642x over previous
#include <cuda_runtime.h>
#include <cuda_bf16.h>
#include <cstdint>

#define Bsz 2
#define Lq 4096
#define Dm 512
#define Hh 8
#define Ee 64
#define NC 32
#define CS 128
#define BHn (Bsz*Hh)

// ---------------- scratch ----------------------------------------------------
__device__ float g_loglam[BHn * Lq];
__device__ float g_cum[BHn * Lq];
__device__ float g_q[BHn * Lq * Ee];
__device__ float g_k[BHn * Lq * Ee];
__device__ float g_v[BHn * Lq * Ee];
__device__ float g_S[BHn * NC * Ee * Ee];
__device__ float g_z[BHn * NC * Ee];
__device__ float g_out2[Bsz * Lq * Dm];
__device__ __align__(16) __nv_bfloat16 g_xhi[Bsz * Lq * Dm];
__device__ __align__(16) __nv_bfloat16 g_xlo[Bsz * Lq * Dm];
__device__ __align__(16) __nv_bfloat16 g_ahi[Bsz * Lq * Dm];
__device__ __align__(16) __nv_bfloat16 g_alo[Bsz * Lq * Dm];
__device__ __align__(16) __nv_bfloat16 g_wq_hi[3 * Dm * Dm];
__device__ __align__(16) __nv_bfloat16 g_wq_lo[3 * Dm * Dm];
__device__ __align__(16) __nv_bfloat16 g_wo_hi[Dm * Dm];
__device__ __align__(16) __nv_bfloat16 g_wo_lo[Dm * Dm];

// ---------------- low-level helpers -------------------------------------------
__device__ __forceinline__ uint32_t smem_u32(const void* p) {
    uint32_t a;
    asm("{ .reg .u64 t; cvta.to.shared.u64 t, %1; cvt.u32.u64 %0, t; }" : "=r"(a) : "l"(p));
    return a;
}
__device__ __forceinline__ void ldsm4(uint32_t* r, uint32_t addr) {
    asm volatile("ldmatrix.sync.aligned.m8n8.x4.shared.b16 {%0,%1,%2,%3}, [%4];"
                 : "=r"(r[0]), "=r"(r[1]), "=r"(r[2]), "=r"(r[3]) : "r"(addr));
}
__device__ __forceinline__ void mma16816(float* d, const uint32_t* a, const uint32_t* b) {
    asm volatile("mma.sync.aligned.m16n8k16.row.col.f32.bf16.bf16.f32 "
                 "{%0,%1,%2,%3}, {%4,%5,%6,%7}, {%8,%9}, {%0,%1,%2,%3};"
                 : "+f"(d[0]), "+f"(d[1]), "+f"(d[2]), "+f"(d[3])
                 : "r"(a[0]), "r"(a[1]), "r"(a[2]), "r"(a[3]), "r"(b[0]), "r"(b[1]));
}
#define CP_ASYNC16(sm, gm) \
    asm volatile("cp.async.cg.shared.global [%0], [%1], 16;" :: "r"(sm), "l"(gm))
#define CP_COMMIT() asm volatile("cp.async.commit_group;" ::: "memory")
#define CP_WAIT(n)  asm volatile("cp.async.wait_group %0;" :: "n"(n) : "memory")

__device__ __forceinline__ void split2(float v0, float v1,
                                       __nv_bfloat162& ph, __nv_bfloat162& pl) {
    __nv_bfloat16 h0 = __float2bfloat16(v0), h1 = __float2bfloat16(v1);
    ph.x = h0; ph.y = h1;
    pl.x = __float2bfloat16(v0 - __bfloat162float(h0));
    pl.y = __float2bfloat16(v1 - __bfloat162float(h1));
}

// ---------------- K0: fused x split + decay logits (one pass over x) ---------
__global__ __launch_bounds__(256) void split_x_decay_kernel(const float* __restrict__ x,
                                                            const float* __restrict__ dw,
                                                            const float* __restrict__ db) {
    int warp = (blockIdx.x * blockDim.x + threadIdx.x) >> 5;   // 0..8191 row
    int lane = threadIdx.x & 31;
    const float4* xr = (const float4*)(x + (size_t)warp * Dm);
    float4 xv[4];
#pragma unroll
    for (int i = 0; i < 4; i++) xv[i] = xr[lane + 32 * i];
    __nv_bfloat162* hi = (__nv_bfloat162*)(g_xhi + (size_t)warp * Dm);
    __nv_bfloat162* lo = (__nv_bfloat162*)(g_xlo + (size_t)warp * Dm);
#pragma unroll
    for (int i = 0; i < 4; i++) {
        int idx = lane + 32 * i;
        __nv_bfloat162 ph0, pl0, ph1, pl1;
        split2(xv[i].x, xv[i].y, ph0, pl0);
        split2(xv[i].z, xv[i].w, ph1, pl1);
        hi[2 * idx] = ph0; hi[2 * idx + 1] = ph1;
        lo[2 * idx] = pl0; lo[2 * idx + 1] = pl1;
    }
    int b = warp >> 12, l = warp & 4095;
#pragma unroll
    for (int h = 0; h < Hh; h++) {
        const float4* wr = (const float4*)(dw + (size_t)h * Dm);
        float p = 0.f;
#pragma unroll
        for (int i = 0; i < 4; i++) {
            float4 w = wr[lane + 32 * i];
            p += xv[i].x * w.x + xv[i].y * w.y + xv[i].z * w.z + xv[i].w * w.w;
        }
#pragma unroll
        for (int o = 16; o; o >>= 1) p += __shfl_xor_sync(0xffffffffu, p, o);
        if (lane == 0) {
            float logit = p + db[h];
            float lam = 0.9f + 0.1f / (1.f + expf(-logit));
            lam = fmaxf(lam, 1e-6f);
            g_loglam[((size_t)(b * Hh + h)) * Lq + l] = logf(lam);
        }
    }
}

// ---------------- K0w: both weight splits in one launch ----------------------
__global__ void split_w_kernel(const float* __restrict__ qkv_w,
                               const float* __restrict__ out_w) {
    int i = blockIdx.x * blockDim.x + threadIdx.x;
    const int nq = 3 * Dm * Dm / 4;
    const float* s; __nv_bfloat16 *hi, *lo; int j;
    if (i < nq) { s = qkv_w; hi = g_wq_hi; lo = g_wq_lo; j = i; }
    else {
        j = i - nq;
        if (j >= Dm * Dm / 4) return;
        s = out_w; hi = g_wo_hi; lo = g_wo_lo;
    }
    float4 v = ((const float4*)s)[j];
    __nv_bfloat162 ph0, pl0, ph1, pl1;
    split2(v.x, v.y, ph0, pl0);
    split2(v.z, v.w, ph1, pl1);
    ((__nv_bfloat162*)hi)[2 * j] = ph0; ((__nv_bfloat162*)hi)[2 * j + 1] = ph1;
    ((__nv_bfloat162*)lo)[2 * j] = pl0; ((__nv_bfloat162*)lo)[2 * j + 1] = pl1;
}

// ---------------- K0b: inclusive scan of log lambda per (b,h), clip ----------
__global__ void cum_scan_kernel() {
    int bh = blockIdx.x;
    int tid = threadIdx.x;
    int lane = tid & 31, w = tid >> 5;
    const float* src = g_loglam + (size_t)bh * Lq + tid * 8;
    float v[8]; float s = 0.f;
#pragma unroll
    for (int j = 0; j < 8; j++) { v[j] = src[j]; s += v[j]; }
    float sc = s;
#pragma unroll
    for (int o = 1; o < 32; o <<= 1) {
        float n = __shfl_up_sync(0xffffffffu, sc, o);
        if (lane >= o) sc += n;
    }
    __shared__ float wt[16];
    if (lane == 31) wt[w] = sc;
    __syncthreads();
    if (tid < 16) {
        float ws = wt[tid];
#pragma unroll
        for (int o = 1; o < 16; o <<= 1) {
            float n = __shfl_up_sync(0xffffu, ws, o);
            if (tid >= o) ws += n;
        }
        wt[tid] = ws;
    }
    __syncthreads();
    float base = ((w > 0) ? wt[w - 1] : 0.f) + sc - s;
    float run = base;
    float* dst = g_cum + (size_t)bh * Lq + tid * 8;
#pragma unroll
    for (int j = 0; j < 8; j++) {
        run += v[j];
        dst[j] = fminf(fmaxf(run, -50.f), 50.f);
    }
}

// ---------------- HMMA GEMM (bf16x3 split), 3-stage swizzled pipeline --------
// smem mat tile: 128 rows x 32 bf16 (64 B/row), 16B-granule swizzle
//   offset(row, g) = row*64 + ((g ^ ((row>>1)&3)) << 4)      [conflict-free]
template <int EPI>
__global__ __launch_bounds__(256, 2) void gemm_mma_kernel(const float* __restrict__ bias) {
    extern __shared__ __align__(16) char dynsmem[];
    constexpr int KD = 512, BK = 32, NKB = KD / BK;   // 16 k-blocks
    constexpr int MATB = 128 * 64;                    // 8192 B per matrix tile
    constexpr int STAGEB = 4 * MATB;                  // 32 KB per stage, 3 stages
    uint32_t sb0 = smem_u32(dynsmem);

    int tid = threadIdx.x;
    int warp = tid >> 5, lane = tid & 31;
    int warp_m = warp & 3, warp_n = warp >> 2;
    int m0 = blockIdx.y * 128, n0 = blockIdx.x * 128;

    const __nv_bfloat16* Ah = (EPI ? g_xhi : g_ahi) + (size_t)m0 * KD;
    const __nv_bfloat16* Al = (EPI ? g_xlo : g_alo) + (size_t)m0 * KD;
    const __nv_bfloat16* Wh = (EPI ? g_wq_hi : g_wo_hi) + (size_t)n0 * KD;
    const __nv_bfloat16* Wl = (EPI ? g_wq_lo : g_wo_lo) + (size_t)n0 * KD;

    float acc[64];
#pragma unroll
    for (int i = 0; i < 64; i++) acc[i] = 0.f;

    auto load_stage = [&](int st, int kb) {
        const __nv_bfloat16* srcs[4] = { Ah, Al, Wh, Wl };
#pragma unroll
        for (int mtx = 0; mtx < 4; mtx++) {
#pragma unroll
            for (int it = 0; it < 2; it++) {
                int q = tid + it * 256;                 // granule id 0..511
                int row = q >> 2, g = q & 3;
                uint32_t dst = sb0 + (uint32_t)((st * 4 + mtx) * MATB + row * 64
                                                + ((g ^ ((row >> 1) & 3)) << 4));
                CP_ASYNC16(dst, srcs[mtx] + (size_t)row * KD + kb * BK + g * 8);
            }
        }
        CP_COMMIT();
    };

    load_stage(0, 0);
    load_stage(1, 1);
    for (int kb = 0; kb < NKB; kb++) {
        if (kb + 1 < NKB) CP_WAIT(1); else CP_WAIT(0);
        __syncthreads();
        if (kb + 2 < NKB) load_stage((kb + 2) % 3, kb + 2);
        uint32_t st = sb0 + (uint32_t)((kb % 3) * STAGEB);
#pragma unroll
        for (int ks = 0; ks < 2; ks++) {
            uint32_t afh[2][4], afl[2][4];
#pragma unroll
            for (int im = 0; im < 2; im++) {
                int row = warp_m * 32 + im * 16 + (lane & 7) + ((lane >> 3) & 1) * 8;
                int gc = ks * 2 + (lane >> 4);          // 16B granule of column
                uint32_t sw = (uint32_t)(row * 64 + ((gc ^ ((row >> 1) & 3)) << 4));
                ldsm4(afh[im], st + 0 * MATB + sw);
                ldsm4(afl[im], st + 1 * MATB + sw);
            }
#pragma unroll
            for (int jn2 = 0; jn2 < 4; jn2++) {
                uint32_t bfh[4], bfl[4];
                int rowb = warp_n * 64 + jn2 * 16 + (lane & 7) + (lane >> 4) * 8;
                int gcb = ks * 2 + ((lane >> 3) & 1);
                uint32_t swb = (uint32_t)(rowb * 64 + ((gcb ^ ((rowb >> 1) & 3)) << 4));
                ldsm4(bfh, st + 2 * MATB + swb);
                ldsm4(bfl, st + 3 * MATB + swb);
#pragma unroll
                for (int im = 0; im < 2; im++) {
#pragma unroll
                    for (int na = 0; na < 2; na++) {
                        float* d = &acc[(im * 8 + jn2 * 2 + na) * 4];
                        mma16816(d, afh[im], bfh + na * 2);
                        mma16816(d, afh[im], bfl + na * 2);
                        mma16816(d, afl[im], bfh + na * 2);
                    }
                }
            }
        }
    }
    __syncthreads();

    float* Csm = (float*)dynsmem;
    {
        int r0 = warp_m * 32 + (lane >> 2);
        int c0 = warp_n * 64 + (lane & 3) * 2;
#pragma unroll
        for (int im = 0; im < 2; im++) {
#pragma unroll
            for (int jn = 0; jn < 8; jn++) {
                float* d = &acc[(im * 8 + jn) * 4];
                int rr = r0 + im * 16, cc = c0 + jn * 8;
                Csm[rr * 132 + cc] = d[0];
                Csm[rr * 132 + cc + 1] = d[1];
                Csm[(rr + 8) * 132 + cc] = d[2];
                Csm[(rr + 8) * 132 + cc + 1] = d[3];
            }
        }
    }
    __syncthreads();

#pragma unroll 4
    for (int it = 0; it < 64; it++) {
        int idx = it * 256 + tid;
        int row = idx >> 7, col = idx & 127;
        float val = Csm[row * 132 + col] + bias[n0 + col];
        int m = m0 + row;
        if (EPI == 0) {
            g_out2[(size_t)m * Dm + n0 + col] = val;
        } else {
            int b = m >> 12, l = m & 4095;
            int n = n0 + col;
            int sec = n >> 9;
            int nn = n & 511;
            int h = nn >> 6, e = nn & 63;
            size_t rowoff = ((size_t)(b * Hh + h) * Lq + l) * Ee + e;
            if (sec == 2) {
                g_v[rowoff] = val;
            } else {
                float cum = g_cum[(size_t)(b * Hh + h) * Lq + l];
                float mul = (sec == 0) ? 0.125f * expf(cum) : expf(-cum);
                float fm = (val > 0.f) ? val + 1.f : expf(val);
                ((sec == 0) ? g_q : g_k)[rowoff] = fm * mul;
            }
        }
    }
}

// ---------------- K2: per-chunk S = KᵀV (64x64), z = Σk ----------------------
__global__ void chunk_sum_kernel() {
    __shared__ float Ks[32][Ee];
    __shared__ float Vs[32][Ee];
    int blk = blockIdx.x;
    int c = blk & (NC - 1);
    int bh = blk >> 5;
    int tid = threadIdx.x;
    int tx = tid & 15, ty = tid >> 4;
    const float* Kb = g_k + ((size_t)bh * Lq + c * CS) * Ee;
    const float* Vb = g_v + ((size_t)bh * Lq + c * CS) * Ee;
    float acc[4][4];
#pragma unroll
    for (int i = 0; i < 4; i++)
#pragma unroll
        for (int j = 0; j < 4; j++) acc[i][j] = 0.f;
    float zacc[4] = {0.f, 0.f, 0.f, 0.f};
    for (int r0 = 0; r0 < CS; r0 += 32) {
#pragma unroll
        for (int u = 0; u < 2; u++) {
            int idx = tid + u * 256;
            ((float4*)Ks)[idx] = ((const float4*)(Kb + r0 * Ee))[idx];
            ((float4*)Vs)[idx] = ((const float4*)(Vb + r0 * Ee))[idx];
        }
        __syncthreads();
#pragma unroll
        for (int r = 0; r < 32; r++) {
            float a[4], bq[4];
#pragma unroll
            for (int i = 0; i < 4; i++) a[i] = Ks[r][ty * 4 + i];
#pragma unroll
            for (int j = 0; j < 4; j++) bq[j] = Vs[r][tx * 4 + j];
#pragma unroll
            for (int i = 0; i < 4; i++) {
                zacc[i] += a[i];
#pragma unroll
                for (int j = 0; j < 4; j++) acc[i][j] += a[i] * bq[j];
            }
        }
        __syncthreads();
    }
    float* Sd = g_S + (size_t)blk * Ee * Ee;
#pragma unroll
    for (int i = 0; i < 4; i++)
#pragma unroll
        for (int j = 0; j < 4; j++) Sd[(ty * 4 + i) * Ee + tx * 4 + j] = acc[i][j];
    if (tx == 0) {
        float* zd = g_z + (size_t)blk * Ee;
#pragma unroll
        for (int i = 0; i < 4; i++) zd[ty * 4 + i] = zacc[i];
    }
}

// ---------------- K3: exclusive prefix over chunks (full-width grid) ---------
__global__ __launch_bounds__(512) void chunk_prefix_kernel() {
    int bh = blockIdx.x;
    int idx = blockIdx.y * 512 + threadIdx.x;
    float* p = g_S + (size_t)bh * NC * (Ee * Ee) + idx;
    float v[NC];
#pragma unroll
    for (int c = 0; c < NC; c++) v[c] = p[(size_t)c * (Ee * Ee)];
    float carry = 0.f;
#pragma unroll
    for (int c = 0; c < NC; c++) { p[(size_t)c * (Ee * Ee)] = carry; carry += v[c]; }
    if (blockIdx.y == 0 && threadIdx.x < Ee) {
        float* pz = g_z + (size_t)bh * NC * Ee + threadIdx.x;
        float zv[NC];
#pragma unroll
        for (int c = 0; c < NC; c++) zv[c] = pz[c * Ee];
        float zc = 0.f;
#pragma unroll
        for (int c = 0; c < NC; c++) { pz[c * Ee] = zc; zc += zv[c]; }
    }
}

// ---------------- K4: chunked causal linear attention (writes bf16 split) ----
__global__ __launch_bounds__(128) void attn_kernel() {
    __shared__ float sh[Ee * Ee + Ee];
    int blk = blockIdx.x;
    int c = blk & 31;
    int bh = blk >> 5;
    int t = threadIdx.x;
    const float* qp = g_q + ((size_t)bh * Lq + c * CS + t) * Ee;
    float q[Ee];
#pragma unroll
    for (int i = 0; i < 16; i++) {
        float4 v4 = ((const float4*)qp)[i];
        q[4 * i] = v4.x; q[4 * i + 1] = v4.y; q[4 * i + 2] = v4.z; q[4 * i + 3] = v4.w;
    }
    const float* Sp = g_S + (size_t)blk * Ee * Ee;
#pragma unroll
    for (int u = 0; u < 8; u++) ((float4*)sh)[t + u * 128] = ((const float4*)Sp)[t + u * 128];
    if (t < 16) ((float4*)(sh + Ee * Ee))[t] = ((const float4*)(g_z + (size_t)blk * Ee))[t];
    __syncthreads();

    float num[Ee];
#pragma unroll
    for (int f = 0; f < Ee; f++) num[f] = 0.f;
    float den = 1e-6f;
#pragma unroll
    for (int e = 0; e < Ee; e++) {
        float qe = q[e];
        den += qe * sh[Ee * Ee + e];
        const float4* srow = (const float4*)(sh + e * Ee);
#pragma unroll
        for (int f4 = 0; f4 < 16; f4++) {
            float4 sv = srow[f4];
            num[4 * f4]     += qe * sv.x;
            num[4 * f4 + 1] += qe * sv.y;
            num[4 * f4 + 2] += qe * sv.z;
            num[4 * f4 + 3] += qe * sv.w;
        }
    }
    __syncthreads();

    const float* Kb = g_k + ((size_t)bh * Lq + c * CS) * Ee;
    const float* Vb = g_v + ((size_t)bh * Lq + c * CS) * Ee;
    for (int s0 = 0; s0 < CS; s0 += 32) {
#pragma unroll
        for (int u = 0; u < 4; u++) {
            int idx = t + u * 128;
            ((float4*)sh)[idx] = ((const float4*)(Kb + s0 * Ee))[idx];
            ((float4*)(sh + 2048))[idx] = ((const float4*)(Vb + s0 * Ee))[idx];
        }
        __syncthreads();
        for (int s = 0; s < 32; s++) {
            if (s0 + s <= t) {
                float a = 0.f;
                const float4* krow = (const float4*)(sh + s * Ee);
#pragma unroll
                for (int e4 = 0; e4 < 16; e4++) {
                    float4 kv = krow[e4];
                    a += q[4 * e4] * kv.x + q[4 * e4 + 1] * kv.y
                       + q[4 * e4 + 2] * kv.z + q[4 * e4 + 3] * kv.w;
                }
                den += a;
                const float4* vrow = (const float4*)(sh + 2048 + s * Ee);
#pragma unroll
                for (int f4 = 0; f4 < 16; f4++) {
                    float4 vv = vrow[f4];
                    num[4 * f4]     += a * vv.x;
                    num[4 * f4 + 1] += a * vv.y;
                    num[4 * f4 + 2] += a * vv.z;
                    num[4 * f4 + 3] += a * vv.w;
                }
            }
        }
        __syncthreads();
    }
    float invd = 1.0f / den;
    int b = bh >> 3, h = bh & 7;
    size_t off = ((size_t)(b * Lq + c * CS + t)) * Dm + h * Ee;
    __nv_bfloat162* oh = (__nv_bfloat162*)(g_ahi + off);
    __nv_bfloat162* ol = (__nv_bfloat162*)(g_alo + off);
#pragma unroll
    for (int f2 = 0; f2 < 32; f2++) {
        float v0 = num[2 * f2] * invd, v1 = num[2 * f2 + 1] * invd;
        __nv_bfloat162 ph, pl;
        split2(v0, v1, ph, pl);
        oh[f2] = ph; ol[f2] = pl;
    }
}

// ---------------- K6: RMSNorm -------------------------------------------------
__global__ void rmsnorm_kernel(const float* __restrict__ scale, float* __restrict__ out) {
    int row = blockIdx.x;
    int tid = threadIdx.x;
    const float* r = g_out2 + (size_t)row * Dm;
    float v0 = r[tid], v1 = r[tid + 256];
    float ss = v0 * v0 + v1 * v1;
#pragma unroll
    for (int o = 16; o; o >>= 1) ss += __shfl_xor_sync(0xffffffffu, ss, o);
    __shared__ float wsum[8];
    __shared__ float rn_s;
    if ((tid & 31) == 0) wsum[tid >> 5] = ss;
    __syncthreads();
    if (tid == 0) {
        float tt = 0.f;
#pragma unroll
        for (int i = 0; i < 8; i++) tt += wsum[i];
        rn_s = rsqrtf(tt * (1.0f / 512.0f) + 1e-8f);
    }
    __syncthreads();
    float rn = rn_s;
    out[(size_t)row * Dm + tid] = v0 * rn * scale[tid];
    out[(size_t)row * Dm + tid + 256] = v1 * rn * scale[tid + 256];
}

// ---------------- launch ------------------------------------------------------
extern "C" void kernel_launch(void* const* d_in, const int* in_sizes, int n_in,
                              void* d_out, int out_size) {
    const float* x          = (const float*)d_in[0];
    const float* qkv_w      = (const float*)d_in[1];
    const float* qkv_b      = (const float*)d_in[2];
    const float* out_w      = (const float*)d_in[3];
    const float* out_b      = (const float*)d_in[4];
    const float* decay_w    = (const float*)d_in[5];
    const float* decay_b    = (const float*)d_in[6];
    const float* norm_scale = (const float*)d_in[7];
    float* out = (float*)d_out;
    (void)in_sizes; (void)n_in; (void)out_size;

    // dynamic smem: max(3 stages x 32 KB = 98304, C staging 67584)
    const int DYN = 98304;
    static bool attr_set = false;
    if (!attr_set) {
        cudaFuncSetAttribute(gemm_mma_kernel<1>, cudaFuncAttributeMaxDynamicSharedMemorySize, DYN);
        cudaFuncSetAttribute(gemm_mma_kernel<0>, cudaFuncAttributeMaxDynamicSharedMemorySize, DYN);
        attr_set = true;
    }

    split_w_kernel<<<1024, 256>>>(qkv_w, out_w);
    split_x_decay_kernel<<<1024, 256>>>(x, decay_w, decay_b);
    cum_scan_kernel<<<BHn, 512>>>();

    gemm_mma_kernel<1><<<dim3(12, 64), 256, DYN>>>(qkv_b);

    chunk_sum_kernel<<<BHn * NC, 256>>>();
    chunk_prefix_kernel<<<dim3(BHn, 8), 512>>>();
    attn_kernel<<<BHn * NC, 128>>>();

    gemm_mma_kernel<0><<<dim3(4, 64), 256, DYN>>>(out_b);

    rmsnorm_kernel<<<Bsz * Lq, 256>>>(norm_scale, out);
}

// round 6
// speedup vs baseline: 1.9060x; 1.0029x over previous
#include <cuda_runtime.h>
#include <cuda_bf16.h>
#include <cstdint>

#define Bsz 2
#define Lq 4096
#define Dm 512
#define Hh 8
#define Ee 64
#define NC 32
#define CS 128
#define BHn (Bsz*Hh)

// ---------------- scratch ----------------------------------------------------
__device__ float g_loglam[BHn * Lq];
__device__ float g_cum[BHn * Lq];
__device__ float g_q[BHn * Lq * Ee];
__device__ float g_k[BHn * Lq * Ee];
__device__ float g_v[BHn * Lq * Ee];
__device__ float g_S[BHn * NC * Ee * Ee];
__device__ float g_z[BHn * NC * Ee];
__device__ float g_out2[Bsz * Lq * Dm];
__device__ __align__(16) __nv_bfloat16 g_xhi[Bsz * Lq * Dm];
__device__ __align__(16) __nv_bfloat16 g_xlo[Bsz * Lq * Dm];
__device__ __align__(16) __nv_bfloat16 g_ahi[Bsz * Lq * Dm];
__device__ __align__(16) __nv_bfloat16 g_alo[Bsz * Lq * Dm];
__device__ __align__(16) __nv_bfloat16 g_wq_hi[3 * Dm * Dm];
__device__ __align__(16) __nv_bfloat16 g_wq_lo[3 * Dm * Dm];
__device__ __align__(16) __nv_bfloat16 g_wo_hi[Dm * Dm];
__device__ __align__(16) __nv_bfloat16 g_wo_lo[Dm * Dm];

// ---------------- low-level helpers -------------------------------------------
__device__ __forceinline__ uint32_t smem_u32(const void* p) {
    uint32_t a;
    asm("{ .reg .u64 t; cvta.to.shared.u64 t, %1; cvt.u32.u64 %0, t; }" : "=r"(a) : "l"(p));
    return a;
}
__device__ __forceinline__ void ldsm4(uint32_t* r, uint32_t addr) {
    asm volatile("ldmatrix.sync.aligned.m8n8.x4.shared.b16 {%0,%1,%2,%3}, [%4];"
                 : "=r"(r[0]), "=r"(r[1]), "=r"(r[2]), "=r"(r[3]) : "r"(addr));
}
__device__ __forceinline__ void mma16816(float* d, const uint32_t* a, const uint32_t* b) {
    asm volatile("mma.sync.aligned.m16n8k16.row.col.f32.bf16.bf16.f32 "
                 "{%0,%1,%2,%3}, {%4,%5,%6,%7}, {%8,%9}, {%0,%1,%2,%3};"
                 : "+f"(d[0]), "+f"(d[1]), "+f"(d[2]), "+f"(d[3])
                 : "r"(a[0]), "r"(a[1]), "r"(a[2]), "r"(a[3]), "r"(b[0]), "r"(b[1]));
}
#define CP_ASYNC16(sm, gm) \
    asm volatile("cp.async.cg.shared.global [%0], [%1], 16;" :: "r"(sm), "l"(gm))
#define CP_COMMIT() asm volatile("cp.async.commit_group;" ::: "memory")
#define CP_WAIT(n)  asm volatile("cp.async.wait_group %0;" :: "n"(n) : "memory")

__device__ __forceinline__ void split2(float v0, float v1,
                                       __nv_bfloat162& ph, __nv_bfloat162& pl) {
    __nv_bfloat16 h0 = __float2bfloat16(v0), h1 = __float2bfloat16(v1);
    ph.x = h0; ph.y = h1;
    pl.x = __float2bfloat16(v0 - __bfloat162float(h0));
    pl.y = __float2bfloat16(v1 - __bfloat162float(h1));
}

// ---------------- K0: fused x split + decay logits (one pass over x) ---------
__global__ __launch_bounds__(256) void split_x_decay_kernel(const float* __restrict__ x,
                                                            const float* __restrict__ dw,
                                                            const float* __restrict__ db) {
    int warp = (blockIdx.x * blockDim.x + threadIdx.x) >> 5;   // 0..8191 row
    int lane = threadIdx.x & 31;
    const float4* xr = (const float4*)(x + (size_t)warp * Dm);
    float4 xv[4];
#pragma unroll
    for (int i = 0; i < 4; i++) xv[i] = xr[lane + 32 * i];
    __nv_bfloat162* hi = (__nv_bfloat162*)(g_xhi + (size_t)warp * Dm);
    __nv_bfloat162* lo = (__nv_bfloat162*)(g_xlo + (size_t)warp * Dm);
#pragma unroll
    for (int i = 0; i < 4; i++) {
        int idx = lane + 32 * i;
        __nv_bfloat162 ph0, pl0, ph1, pl1;
        split2(xv[i].x, xv[i].y, ph0, pl0);
        split2(xv[i].z, xv[i].w, ph1, pl1);
        hi[2 * idx] = ph0; hi[2 * idx + 1] = ph1;
        lo[2 * idx] = pl0; lo[2 * idx + 1] = pl1;
    }
    int b = warp >> 12, l = warp & 4095;
#pragma unroll
    for (int h = 0; h < Hh; h++) {
        const float4* wr = (const float4*)(dw + (size_t)h * Dm);
        float p = 0.f;
#pragma unroll
        for (int i = 0; i < 4; i++) {
            float4 w = wr[lane + 32 * i];
            p += xv[i].x * w.x + xv[i].y * w.y + xv[i].z * w.z + xv[i].w * w.w;
        }
#pragma unroll
        for (int o = 16; o; o >>= 1) p += __shfl_xor_sync(0xffffffffu, p, o);
        if (lane == 0) {
            float logit = p + db[h];
            float lam = 0.9f + 0.1f / (1.f + expf(-logit));
            lam = fmaxf(lam, 1e-6f);
            g_loglam[((size_t)(b * Hh + h)) * Lq + l] = logf(lam);
        }
    }
}

// ---------------- K0w: both weight splits in one launch ----------------------
__global__ void split_w_kernel(const float* __restrict__ qkv_w,
                               const float* __restrict__ out_w) {
    int i = blockIdx.x * blockDim.x + threadIdx.x;
    const int nq = 3 * Dm * Dm / 4;
    const float* s; __nv_bfloat16 *hi, *lo; int j;
    if (i < nq) { s = qkv_w; hi = g_wq_hi; lo = g_wq_lo; j = i; }
    else {
        j = i - nq;
        if (j >= Dm * Dm / 4) return;
        s = out_w; hi = g_wo_hi; lo = g_wo_lo;
    }
    float4 v = ((const float4*)s)[j];
    __nv_bfloat162 ph0, pl0, ph1, pl1;
    split2(v.x, v.y, ph0, pl0);
    split2(v.z, v.w, ph1, pl1);
    ((__nv_bfloat162*)hi)[2 * j] = ph0; ((__nv_bfloat162*)hi)[2 * j + 1] = ph1;
    ((__nv_bfloat162*)lo)[2 * j] = pl0; ((__nv_bfloat162*)lo)[2 * j + 1] = pl1;
}

// ---------------- K0b: inclusive scan of log lambda per (b,h), clip ----------
__global__ void cum_scan_kernel() {
    int bh = blockIdx.x;
    int tid = threadIdx.x;
    int lane = tid & 31, w = tid >> 5;
    const float* src = g_loglam + (size_t)bh * Lq + tid * 8;
    float v[8]; float s = 0.f;
#pragma unroll
    for (int j = 0; j < 8; j++) { v[j] = src[j]; s += v[j]; }
    float sc = s;
#pragma unroll
    for (int o = 1; o < 32; o <<= 1) {
        float n = __shfl_up_sync(0xffffffffu, sc, o);
        if (lane >= o) sc += n;
    }
    __shared__ float wt[16];
    if (lane == 31) wt[w] = sc;
    __syncthreads();
    if (tid < 16) {
        float ws = wt[tid];
#pragma unroll
        for (int o = 1; o < 16; o <<= 1) {
            float n = __shfl_up_sync(0xffffu, ws, o);
            if (tid >= o) ws += n;
        }
        wt[tid] = ws;
    }
    __syncthreads();
    float base = ((w > 0) ? wt[w - 1] : 0.f) + sc - s;
    float run = base;
    float* dst = g_cum + (size_t)bh * Lq + tid * 8;
#pragma unroll
    for (int j = 0; j < 8; j++) {
        run += v[j];
        dst[j] = fminf(fmaxf(run, -50.f), 50.f);
    }
}

// ---------------- HMMA GEMM (bf16x3 split), 3-stage swizzled pipeline --------
// Term-major MMA ordering: accumulator reuse distance 4 (hides HMMA latency).
template <int EPI>
__global__ __launch_bounds__(256, 2) void gemm_mma_kernel(const float* __restrict__ bias) {
    extern __shared__ __align__(16) char dynsmem[];
    constexpr int KD = 512, BK = 32, NKB = KD / BK;   // 16 k-blocks
    constexpr int MATB = 128 * 64;                    // 8192 B per matrix tile
    constexpr int STAGEB = 4 * MATB;                  // 32 KB per stage, 3 stages
    uint32_t sb0 = smem_u32(dynsmem);

    int tid = threadIdx.x;
    int warp = tid >> 5, lane = tid & 31;
    int warp_m = warp & 3, warp_n = warp >> 2;
    int m0 = blockIdx.y * 128, n0 = blockIdx.x * 128;

    const __nv_bfloat16* Ah = (EPI ? g_xhi : g_ahi) + (size_t)m0 * KD;
    const __nv_bfloat16* Al = (EPI ? g_xlo : g_alo) + (size_t)m0 * KD;
    const __nv_bfloat16* Wh = (EPI ? g_wq_hi : g_wo_hi) + (size_t)n0 * KD;
    const __nv_bfloat16* Wl = (EPI ? g_wq_lo : g_wo_lo) + (size_t)n0 * KD;

    float acc[64];
#pragma unroll
    for (int i = 0; i < 64; i++) acc[i] = 0.f;

    auto load_stage = [&](int st, int kb) {
        const __nv_bfloat16* srcs[4] = { Ah, Al, Wh, Wl };
#pragma unroll
        for (int mtx = 0; mtx < 4; mtx++) {
#pragma unroll
            for (int it = 0; it < 2; it++) {
                int q = tid + it * 256;                 // granule id 0..511
                int row = q >> 2, g = q & 3;
                uint32_t dst = sb0 + (uint32_t)((st * 4 + mtx) * MATB + row * 64
                                                + ((g ^ ((row >> 1) & 3)) << 4));
                CP_ASYNC16(dst, srcs[mtx] + (size_t)row * KD + kb * BK + g * 8);
            }
        }
        CP_COMMIT();
    };

    load_stage(0, 0);
    load_stage(1, 1);
    for (int kb = 0; kb < NKB; kb++) {
        if (kb + 1 < NKB) CP_WAIT(1); else CP_WAIT(0);
        __syncthreads();
        if (kb + 2 < NKB) load_stage((kb + 2) % 3, kb + 2);
        uint32_t st = sb0 + (uint32_t)((kb % 3) * STAGEB);
#pragma unroll
        for (int ks = 0; ks < 2; ks++) {
            uint32_t afh[2][4], afl[2][4];
#pragma unroll
            for (int im = 0; im < 2; im++) {
                int row = warp_m * 32 + im * 16 + (lane & 7) + ((lane >> 3) & 1) * 8;
                int gc = ks * 2 + (lane >> 4);
                uint32_t sw = (uint32_t)(row * 64 + ((gc ^ ((row >> 1) & 3)) << 4));
                ldsm4(afh[im], st + 0 * MATB + sw);
                ldsm4(afl[im], st + 1 * MATB + sw);
            }
#pragma unroll
            for (int jn2 = 0; jn2 < 4; jn2++) {
                uint32_t bfh[4], bfl[4];
                int rowb = warp_n * 64 + jn2 * 16 + (lane & 7) + (lane >> 4) * 8;
                int gcb = ks * 2 + ((lane >> 3) & 1);
                uint32_t swb = (uint32_t)(rowb * 64 + ((gcb ^ ((rowb >> 1) & 3)) << 4));
                ldsm4(bfh, st + 2 * MATB + swb);
                ldsm4(bfl, st + 3 * MATB + swb);
                // term-major: 4 independent accumulators between reuses
#pragma unroll
                for (int im = 0; im < 2; im++)
#pragma unroll
                    for (int na = 0; na < 2; na++)
                        mma16816(&acc[(im * 8 + jn2 * 2 + na) * 4], afh[im], bfh + na * 2);
#pragma unroll
                for (int im = 0; im < 2; im++)
#pragma unroll
                    for (int na = 0; na < 2; na++)
                        mma16816(&acc[(im * 8 + jn2 * 2 + na) * 4], afh[im], bfl + na * 2);
#pragma unroll
                for (int im = 0; im < 2; im++)
#pragma unroll
                    for (int na = 0; na < 2; na++)
                        mma16816(&acc[(im * 8 + jn2 * 2 + na) * 4], afl[im], bfh + na * 2);
            }
        }
    }
    __syncthreads();

    float* Csm = (float*)dynsmem;
    {
        int r0 = warp_m * 32 + (lane >> 2);
        int c0 = warp_n * 64 + (lane & 3) * 2;
#pragma unroll
        for (int im = 0; im < 2; im++) {
#pragma unroll
            for (int jn = 0; jn < 8; jn++) {
                float* d = &acc[(im * 8 + jn) * 4];
                int rr = r0 + im * 16, cc = c0 + jn * 8;
                Csm[rr * 132 + cc] = d[0];
                Csm[rr * 132 + cc + 1] = d[1];
                Csm[(rr + 8) * 132 + cc] = d[2];
                Csm[(rr + 8) * 132 + cc + 1] = d[3];
            }
        }
    }
    __syncthreads();

#pragma unroll 4
    for (int it = 0; it < 64; it++) {
        int idx = it * 256 + tid;
        int row = idx >> 7, col = idx & 127;
        float val = Csm[row * 132 + col] + bias[n0 + col];
        int m = m0 + row;
        if (EPI == 0) {
            g_out2[(size_t)m * Dm + n0 + col] = val;
        } else {
            int b = m >> 12, l = m & 4095;
            int n = n0 + col;
            int sec = n >> 9;
            int nn = n & 511;
            int h = nn >> 6, e = nn & 63;
            size_t rowoff = ((size_t)(b * Hh + h) * Lq + l) * Ee + e;
            if (sec == 2) {
                g_v[rowoff] = val;
            } else {
                float cum = g_cum[(size_t)(b * Hh + h) * Lq + l];
                float mul = (sec == 0) ? 0.125f * expf(cum) : expf(-cum);
                float fm = (val > 0.f) ? val + 1.f : expf(val);
                ((sec == 0) ? g_q : g_k)[rowoff] = fm * mul;
            }
        }
    }
}

// ---------------- K2: per-chunk S = KᵀV (64x64), z = Σk ----------------------
__global__ void chunk_sum_kernel() {
    __shared__ float Ks[32][Ee];
    __shared__ float Vs[32][Ee];
    int blk = blockIdx.x;
    int c = blk & (NC - 1);
    int bh = blk >> 5;
    int tid = threadIdx.x;
    int tx = tid & 15, ty = tid >> 4;
    const float* Kb = g_k + ((size_t)bh * Lq + c * CS) * Ee;
    const float* Vb = g_v + ((size_t)bh * Lq + c * CS) * Ee;
    float acc[4][4];
#pragma unroll
    for (int i = 0; i < 4; i++)
#pragma unroll
        for (int j = 0; j < 4; j++) acc[i][j] = 0.f;
    float zacc[4] = {0.f, 0.f, 0.f, 0.f};
    for (int r0 = 0; r0 < CS; r0 += 32) {
#pragma unroll
        for (int u = 0; u < 2; u++) {
            int idx = tid + u * 256;
            ((float4*)Ks)[idx] = ((const float4*)(Kb + r0 * Ee))[idx];
            ((float4*)Vs)[idx] = ((const float4*)(Vb + r0 * Ee))[idx];
        }
        __syncthreads();
#pragma unroll
        for (int r = 0; r < 32; r++) {
            float a[4], bq[4];
#pragma unroll
            for (int i = 0; i < 4; i++) a[i] = Ks[r][ty * 4 + i];
#pragma unroll
            for (int j = 0; j < 4; j++) bq[j] = Vs[r][tx * 4 + j];
#pragma unroll
            for (int i = 0; i < 4; i++) {
                zacc[i] += a[i];
#pragma unroll
                for (int j = 0; j < 4; j++) acc[i][j] += a[i] * bq[j];
            }
        }
        __syncthreads();
    }
    float* Sd = g_S + (size_t)blk * Ee * Ee;
#pragma unroll
    for (int i = 0; i < 4; i++)
#pragma unroll
        for (int j = 0; j < 4; j++) Sd[(ty * 4 + i) * Ee + tx * 4 + j] = acc[i][j];
    if (tx == 0) {
        float* zd = g_z + (size_t)blk * Ee;
#pragma unroll
        for (int i = 0; i < 4; i++) zd[ty * 4 + i] = zacc[i];
    }
}

// ---------------- K3: exclusive prefix over chunks (full-width grid) ---------
__global__ __launch_bounds__(512) void chunk_prefix_kernel() {
    int bh = blockIdx.x;
    int idx = blockIdx.y * 512 + threadIdx.x;
    float* p = g_S + (size_t)bh * NC * (Ee * Ee) + idx;
    float v[NC];
#pragma unroll
    for (int c = 0; c < NC; c++) v[c] = p[(size_t)c * (Ee * Ee)];
    float carry = 0.f;
#pragma unroll
    for (int c = 0; c < NC; c++) { p[(size_t)c * (Ee * Ee)] = carry; carry += v[c]; }
    if (blockIdx.y == 0 && threadIdx.x < Ee) {
        float* pz = g_z + (size_t)bh * NC * Ee + threadIdx.x;
        float zv[NC];
#pragma unroll
        for (int c = 0; c < NC; c++) zv[c] = pz[c * Ee];
        float zc = 0.f;
#pragma unroll
        for (int c = 0; c < NC; c++) { pz[c * Ee] = zc; zc += zv[c]; }
    }
}

// ---------------- K4: chunked causal linear attention (writes bf16 split) ----
__global__ __launch_bounds__(128) void attn_kernel() {
    __shared__ float sh[Ee * Ee + Ee];
    int blk = blockIdx.x;
    int c = blk & 31;
    int bh = blk >> 5;
    int t = threadIdx.x;
    const float* qp = g_q + ((size_t)bh * Lq + c * CS + t) * Ee;
    float q[Ee];
#pragma unroll
    for (int i = 0; i < 16; i++) {
        float4 v4 = ((const float4*)qp)[i];
        q[4 * i] = v4.x; q[4 * i + 1] = v4.y; q[4 * i + 2] = v4.z; q[4 * i + 3] = v4.w;
    }
    const float* Sp = g_S + (size_t)blk * Ee * Ee;
#pragma unroll
    for (int u = 0; u < 8; u++) ((float4*)sh)[t + u * 128] = ((const float4*)Sp)[t + u * 128];
    if (t < 16) ((float4*)(sh + Ee * Ee))[t] = ((const float4*)(g_z + (size_t)blk * Ee))[t];
    __syncthreads();

    float num[Ee];
#pragma unroll
    for (int f = 0; f < Ee; f++) num[f] = 0.f;
    float den = 1e-6f;
#pragma unroll
    for (int e = 0; e < Ee; e++) {
        float qe = q[e];
        den += qe * sh[Ee * Ee + e];
        const float4* srow = (const float4*)(sh + e * Ee);
#pragma unroll
        for (int f4 = 0; f4 < 16; f4++) {
            float4 sv = srow[f4];
            num[4 * f4]     += qe * sv.x;
            num[4 * f4 + 1] += qe * sv.y;
            num[4 * f4 + 2] += qe * sv.z;
            num[4 * f4 + 3] += qe * sv.w;
        }
    }
    __syncthreads();

    const float* Kb = g_k + ((size_t)bh * Lq + c * CS) * Ee;
    const float* Vb = g_v + ((size_t)bh * Lq + c * CS) * Ee;
    for (int s0 = 0; s0 < CS; s0 += 32) {
#pragma unroll
        for (int u = 0; u < 4; u++) {
            int idx = t + u * 128;
            ((float4*)sh)[idx] = ((const float4*)(Kb + s0 * Ee))[idx];
            ((float4*)(sh + 2048))[idx] = ((const float4*)(Vb + s0 * Ee))[idx];
        }
        __syncthreads();
        for (int s = 0; s < 32; s++) {
            if (s0 + s <= t) {
                float a = 0.f;
                const float4* krow = (const float4*)(sh + s * Ee);
#pragma unroll
                for (int e4 = 0; e4 < 16; e4++) {
                    float4 kv = krow[e4];
                    a += q[4 * e4] * kv.x + q[4 * e4 + 1] * kv.y
                       + q[4 * e4 + 2] * kv.z + q[4 * e4 + 3] * kv.w;
                }
                den += a;
                const float4* vrow = (const float4*)(sh + 2048 + s * Ee);
#pragma unroll
                for (int f4 = 0; f4 < 16; f4++) {
                    float4 vv = vrow[f4];
                    num[4 * f4]     += a * vv.x;
                    num[4 * f4 + 1] += a * vv.y;
                    num[4 * f4 + 2] += a * vv.z;
                    num[4 * f4 + 3] += a * vv.w;
                }
            }
        }
        __syncthreads();
    }
    float invd = 1.0f / den;
    int b = bh >> 3, h = bh & 7;
    size_t off = ((size_t)(b * Lq + c * CS + t)) * Dm + h * Ee;
    __nv_bfloat162* oh = (__nv_bfloat162*)(g_ahi + off);
    __nv_bfloat162* ol = (__nv_bfloat162*)(g_alo + off);
#pragma unroll
    for (int f2 = 0; f2 < 32; f2++) {
        float v0 = num[2 * f2] * invd, v1 = num[2 * f2 + 1] * invd;
        __nv_bfloat162 ph, pl;
        split2(v0, v1, ph, pl);
        oh[f2] = ph; ol[f2] = pl;
    }
}

// ---------------- K6: RMSNorm -------------------------------------------------
__global__ void rmsnorm_kernel(const float* __restrict__ scale, float* __restrict__ out) {
    int row = blockIdx.x;
    int tid = threadIdx.x;
    const float* r = g_out2 + (size_t)row * Dm;
    float v0 = r[tid], v1 = r[tid + 256];
    float ss = v0 * v0 + v1 * v1;
#pragma unroll
    for (int o = 16; o; o >>= 1) ss += __shfl_xor_sync(0xffffffffu, ss, o);
    __shared__ float wsum[8];
    __shared__ float rn_s;
    if ((tid & 31) == 0) wsum[tid >> 5] = ss;
    __syncthreads();
    if (tid == 0) {
        float tt = 0.f;
#pragma unroll
        for (int i = 0; i < 8; i++) tt += wsum[i];
        rn_s = rsqrtf(tt * (1.0f / 512.0f) + 1e-8f);
    }
    __syncthreads();
    float rn = rn_s;
    out[(size_t)row * Dm + tid] = v0 * rn * scale[tid];
    out[(size_t)row * Dm + tid + 256] = v1 * rn * scale[tid + 256];
}

// ---------------- launch ------------------------------------------------------
extern "C" void kernel_launch(void* const* d_in, const int* in_sizes, int n_in,
                              void* d_out, int out_size) {
    const float* x          = (const float*)d_in[0];
    const float* qkv_w      = (const float*)d_in[1];
    const float* qkv_b      = (const float*)d_in[2];
    const float* out_w      = (const float*)d_in[3];
    const float* out_b      = (const float*)d_in[4];
    const float* decay_w    = (const float*)d_in[5];
    const float* decay_b    = (const float*)d_in[6];
    const float* norm_scale = (const float*)d_in[7];
    float* out = (float*)d_out;
    (void)in_sizes; (void)n_in; (void)out_size;

    const int DYN = 98304;
    static bool attr_set = false;
    if (!attr_set) {
        cudaFuncSetAttribute(gemm_mma_kernel<1>, cudaFuncAttributeMaxDynamicSharedMemorySize, DYN);
        cudaFuncSetAttribute(gemm_mma_kernel<0>, cudaFuncAttributeMaxDynamicSharedMemorySize, DYN);
        attr_set = true;
    }

    split_w_kernel<<<1024, 256>>>(qkv_w, out_w);
    split_x_decay_kernel<<<1024, 256>>>(x, decay_w, decay_b);
    cum_scan_kernel<<<BHn, 512>>>();

    gemm_mma_kernel<1><<<dim3(12, 64), 256, DYN>>>(qkv_b);

    chunk_sum_kernel<<<BHn * NC, 256>>>();
    chunk_prefix_kernel<<<dim3(BHn, 8), 512>>>();
    attn_kernel<<<BHn * NC, 128>>>();

    gemm_mma_kernel<0><<<dim3(4, 64), 256, DYN>>>(out_b);

    rmsnorm_kernel<<<Bsz * Lq, 256>>>(norm_scale, out);
}

// round 8
// speedup vs baseline: 1.9663x; 1.0316x over previous
#include <cuda_runtime.h>
#include <cuda_bf16.h>
#include <cstdint>

#define Bsz 2
#define Lq 4096
#define Dm 512
#define Hh 8
#define Ee 64
#define NC 32
#define CS 128
#define BHn (Bsz*Hh)

// ---------------- scratch ----------------------------------------------------
__device__ float g_loglam[BHn * Lq];
__device__ float g_cum[BHn * Lq];
__device__ float g_q[BHn * Lq * Ee];
__device__ float g_k[BHn * Lq * Ee];
__device__ float g_v[BHn * Lq * Ee];
__device__ float g_S[BHn * NC * Ee * Ee];
__device__ float g_z[BHn * NC * Ee];
__device__ float g_out2[Bsz * Lq * Dm];
__device__ __align__(16) __nv_bfloat16 g_xhi[Bsz * Lq * Dm];
__device__ __align__(16) __nv_bfloat16 g_xlo[Bsz * Lq * Dm];
__device__ __align__(16) __nv_bfloat16 g_ahi[Bsz * Lq * Dm];
__device__ __align__(16) __nv_bfloat16 g_alo[Bsz * Lq * Dm];
__device__ __align__(16) __nv_bfloat16 g_wq_hi[3 * Dm * Dm];
__device__ __align__(16) __nv_bfloat16 g_wq_lo[3 * Dm * Dm];
__device__ __align__(16) __nv_bfloat16 g_wo_hi[Dm * Dm];
__device__ __align__(16) __nv_bfloat16 g_wo_lo[Dm * Dm];

// ---------------- low-level helpers -------------------------------------------
__device__ __forceinline__ uint32_t smem_u32(const void* p) {
    uint32_t a;
    asm("{ .reg .u64 t; cvta.to.shared.u64 t, %1; cvt.u32.u64 %0, t; }" : "=r"(a) : "l"(p));
    return a;
}
__device__ __forceinline__ void ldsm4(uint32_t* r, uint32_t addr) {
    asm volatile("ldmatrix.sync.aligned.m8n8.x4.shared.b16 {%0,%1,%2,%3}, [%4];"
                 : "=r"(r[0]), "=r"(r[1]), "=r"(r[2]), "=r"(r[3]) : "r"(addr));
}
__device__ __forceinline__ void mma16816(float* d, const uint32_t* a, const uint32_t* b) {
    asm volatile("mma.sync.aligned.m16n8k16.row.col.f32.bf16.bf16.f32 "
                 "{%0,%1,%2,%3}, {%4,%5,%6,%7}, {%8,%9}, {%0,%1,%2,%3};"
                 : "+f"(d[0]), "+f"(d[1]), "+f"(d[2]), "+f"(d[3])
                 : "r"(a[0]), "r"(a[1]), "r"(a[2]), "r"(a[3]), "r"(b[0]), "r"(b[1]));
}
#define CP_ASYNC16(sm, gm) \
    asm volatile("cp.async.cg.shared.global [%0], [%1], 16;" :: "r"(sm), "l"(gm))
#define CP_COMMIT() asm volatile("cp.async.commit_group;" ::: "memory")
#define CP_WAIT(n)  asm volatile("cp.async.wait_group %0;" :: "n"(n) : "memory")

__device__ __forceinline__ void split2(float v0, float v1,
                                       __nv_bfloat162& ph, __nv_bfloat162& pl) {
    __nv_bfloat16 h0 = __float2bfloat16(v0), h1 = __float2bfloat16(v1);
    ph.x = h0; ph.y = h1;
    pl.x = __float2bfloat16(v0 - __bfloat162float(h0));
    pl.y = __float2bfloat16(v1 - __bfloat162float(h1));
}

// ---------------- K0: fused x split + decay logits (one pass over x) ---------
__global__ __launch_bounds__(256) void split_x_decay_kernel(const float* __restrict__ x,
                                                            const float* __restrict__ dw,
                                                            const float* __restrict__ db) {
    int warp = (blockIdx.x * blockDim.x + threadIdx.x) >> 5;   // 0..8191 row
    int lane = threadIdx.x & 31;
    const float4* xr = (const float4*)(x + (size_t)warp * Dm);
    float4 xv[4];
#pragma unroll
    for (int i = 0; i < 4; i++) xv[i] = xr[lane + 32 * i];
    __nv_bfloat162* hi = (__nv_bfloat162*)(g_xhi + (size_t)warp * Dm);
    __nv_bfloat162* lo = (__nv_bfloat162*)(g_xlo + (size_t)warp * Dm);
#pragma unroll
    for (int i = 0; i < 4; i++) {
        int idx = lane + 32 * i;
        __nv_bfloat162 ph0, pl0, ph1, pl1;
        split2(xv[i].x, xv[i].y, ph0, pl0);
        split2(xv[i].z, xv[i].w, ph1, pl1);
        hi[2 * idx] = ph0; hi[2 * idx + 1] = ph1;
        lo[2 * idx] = pl0; lo[2 * idx + 1] = pl1;
    }
    int b = warp >> 12, l = warp & 4095;
#pragma unroll
    for (int h = 0; h < Hh; h++) {
        const float4* wr = (const float4*)(dw + (size_t)h * Dm);
        float p = 0.f;
#pragma unroll
        for (int i = 0; i < 4; i++) {
            float4 w = wr[lane + 32 * i];
            p += xv[i].x * w.x + xv[i].y * w.y + xv[i].z * w.z + xv[i].w * w.w;
        }
#pragma unroll
        for (int o = 16; o; o >>= 1) p += __shfl_xor_sync(0xffffffffu, p, o);
        if (lane == 0) {
            float logit = p + db[h];
            float lam = 0.9f + 0.1f / (1.f + expf(-logit));
            lam = fmaxf(lam, 1e-6f);
            g_loglam[((size_t)(b * Hh + h)) * Lq + l] = logf(lam);
        }
    }
}

// ---------------- K0w: both weight splits in one launch ----------------------
__global__ void split_w_kernel(const float* __restrict__ qkv_w,
                               const float* __restrict__ out_w) {
    int i = blockIdx.x * blockDim.x + threadIdx.x;
    const int nq = 3 * Dm * Dm / 4;
    const float* s; __nv_bfloat16 *hi, *lo; int j;
    if (i < nq) { s = qkv_w; hi = g_wq_hi; lo = g_wq_lo; j = i; }
    else {
        j = i - nq;
        if (j >= Dm * Dm / 4) return;
        s = out_w; hi = g_wo_hi; lo = g_wo_lo;
    }
    float4 v = ((const float4*)s)[j];
    __nv_bfloat162 ph0, pl0, ph1, pl1;
    split2(v.x, v.y, ph0, pl0);
    split2(v.z, v.w, ph1, pl1);
    ((__nv_bfloat162*)hi)[2 * j] = ph0; ((__nv_bfloat162*)hi)[2 * j + 1] = ph1;
    ((__nv_bfloat162*)lo)[2 * j] = pl0; ((__nv_bfloat162*)lo)[2 * j + 1] = pl1;
}

// ---------------- K0b: inclusive scan of log lambda per (b,h), clip ----------
__global__ void cum_scan_kernel() {
    int bh = blockIdx.x;
    int tid = threadIdx.x;
    int lane = tid & 31, w = tid >> 5;
    const float* src = g_loglam + (size_t)bh * Lq + tid * 8;
    float v[8]; float s = 0.f;
#pragma unroll
    for (int j = 0; j < 8; j++) { v[j] = src[j]; s += v[j]; }
    float sc = s;
#pragma unroll
    for (int o = 1; o < 32; o <<= 1) {
        float n = __shfl_up_sync(0xffffffffu, sc, o);
        if (lane >= o) sc += n;
    }
    __shared__ float wt[16];
    if (lane == 31) wt[w] = sc;
    __syncthreads();
    if (tid < 16) {
        float ws = wt[tid];
#pragma unroll
        for (int o = 1; o < 16; o <<= 1) {
            float n = __shfl_up_sync(0xffffu, ws, o);
            if (tid >= o) ws += n;
        }
        wt[tid] = ws;
    }
    __syncthreads();
    float base = ((w > 0) ? wt[w - 1] : 0.f) + sc - s;
    float run = base;
    float* dst = g_cum + (size_t)bh * Lq + tid * 8;
#pragma unroll
    for (int j = 0; j < 8; j++) {
        run += v[j];
        dst[j] = fminf(fmaxf(run, -50.f), 50.f);
    }
}

// ---------------- HMMA GEMM (bf16x3 split), 128x64 tile, occupancy 3 ---------
// smem per stage: Ah(8K) Al(8K) Wh(4K) Wl(4K) = 24 KB; 3 stages = 72 KB
template <int EPI>
__global__ __launch_bounds__(256, 3) void gemm_mma_kernel(const float* __restrict__ bias) {
    extern __shared__ __align__(16) char dynsmem[];
    constexpr int KD = 512, BK = 32, NKB = KD / BK;   // 16 k-blocks
    constexpr int AOFF = 0, ALOFF = 8192, WOFF = 16384, WLOFF = 20480;
    constexpr int STAGEB = 24576;
    uint32_t sb0 = smem_u32(dynsmem);

    int tid = threadIdx.x;
    int warp = tid >> 5, lane = tid & 31;
    int warp_m = warp & 3, warp_n = warp >> 2;        // 4 x 2, warp tile 32m x 32n
    int m0 = blockIdx.y * 128, n0 = blockIdx.x * 64;

    const __nv_bfloat16* Ah = (EPI ? g_xhi : g_ahi) + (size_t)m0 * KD;
    const __nv_bfloat16* Al = (EPI ? g_xlo : g_alo) + (size_t)m0 * KD;
    const __nv_bfloat16* Wh = (EPI ? g_wq_hi : g_wo_hi) + (size_t)n0 * KD;
    const __nv_bfloat16* Wl = (EPI ? g_wq_lo : g_wo_lo) + (size_t)n0 * KD;

    float acc[32];
#pragma unroll
    for (int i = 0; i < 32; i++) acc[i] = 0.f;

    auto load_stage = [&](int st, int kb) {
        uint32_t base = sb0 + (uint32_t)(st * STAGEB);
        // A matrices: 128 rows x 4 granules x 2 mats
#pragma unroll
        for (int mtx = 0; mtx < 2; mtx++) {
            const __nv_bfloat16* src = mtx ? Al : Ah;
#pragma unroll
            for (int it = 0; it < 2; it++) {
                int q = tid + it * 256;              // 0..511
                int row = q >> 2, g = q & 3;
                uint32_t dst = base + (uint32_t)(mtx * ALOFF + row * 64
                                                 + ((g ^ ((row >> 1) & 3)) << 4));
                CP_ASYNC16(dst, src + (size_t)row * KD + kb * BK + g * 8);
            }
        }
        // W matrices: 64 rows x 4 granules x 2 mats
#pragma unroll
        for (int mtx = 0; mtx < 2; mtx++) {
            const __nv_bfloat16* src = mtx ? Wl : Wh;
            int row = tid >> 2, g = tid & 3;         // 256 granules
            uint32_t dst = base + (uint32_t)(WOFF + mtx * 4096 + row * 64
                                             + ((g ^ ((row >> 1) & 3)) << 4));
            CP_ASYNC16(dst, src + (size_t)row * KD + kb * BK + g * 8);
        }
        CP_COMMIT();
    };

    load_stage(0, 0);
    load_stage(1, 1);
    for (int kb = 0; kb < NKB; kb++) {
        if (kb + 1 < NKB) CP_WAIT(1); else CP_WAIT(0);
        __syncthreads();
        if (kb + 2 < NKB) load_stage((kb + 2) % 3, kb + 2);
        uint32_t st = sb0 + (uint32_t)((kb % 3) * STAGEB);
#pragma unroll
        for (int ks = 0; ks < 2; ks++) {
            uint32_t afh[2][4], afl[2][4];
#pragma unroll
            for (int im = 0; im < 2; im++) {
                int row = warp_m * 32 + im * 16 + (lane & 7) + ((lane >> 3) & 1) * 8;
                int gc = ks * 2 + (lane >> 4);
                uint32_t sw = (uint32_t)(row * 64 + ((gc ^ ((row >> 1) & 3)) << 4));
                ldsm4(afh[im], st + AOFF + sw);
                ldsm4(afl[im], st + ALOFF + sw);
            }
#pragma unroll
            for (int jn2 = 0; jn2 < 2; jn2++) {
                uint32_t bfh[4], bfl[4];
                int rowb = warp_n * 32 + jn2 * 16 + (lane & 7) + (lane >> 4) * 8;
                int gcb = ks * 2 + ((lane >> 3) & 1);
                uint32_t swb = (uint32_t)(rowb * 64 + ((gcb ^ ((rowb >> 1) & 3)) << 4));
                ldsm4(bfh, st + WOFF + swb);
                ldsm4(bfl, st + WLOFF + swb);
#pragma unroll
                for (int im = 0; im < 2; im++) {
#pragma unroll
                    for (int na = 0; na < 2; na++) {
                        float* d = &acc[(im * 4 + jn2 * 2 + na) * 4];
                        mma16816(d, afh[im], bfh + na * 2);
                        mma16816(d, afh[im], bfl + na * 2);
                        mma16816(d, afl[im], bfh + na * 2);
                    }
                }
            }
        }
    }
    __syncthreads();

    // ---- stage C through smem (128 x 68 fp32 = 34.8 KB, reuse pipeline smem) -
    float* Csm = (float*)dynsmem;
    {
        int r0 = warp_m * 32 + (lane >> 2);
        int c0 = warp_n * 32 + (lane & 3) * 2;
#pragma unroll
        for (int im = 0; im < 2; im++) {
#pragma unroll
            for (int jn = 0; jn < 4; jn++) {
                float* d = &acc[(im * 4 + jn) * 4];
                int rr = r0 + im * 16, cc = c0 + jn * 8;
                Csm[rr * 68 + cc] = d[0];
                Csm[rr * 68 + cc + 1] = d[1];
                Csm[(rr + 8) * 68 + cc] = d[2];
                Csm[(rr + 8) * 68 + cc + 1] = d[3];
            }
        }
    }
    __syncthreads();

    // block covers a single (sec, head) since BN=64 divides both boundaries
    int sec = 0, h0 = 0;
    if (EPI == 1) { sec = n0 >> 9; h0 = (n0 & 511) >> 6; }
#pragma unroll 4
    for (int it = 0; it < 32; it++) {
        int idx = it * 256 + tid;
        int row = idx >> 6, col = idx & 63;
        float val = Csm[row * 68 + col] + bias[n0 + col];
        int m = m0 + row;
        if (EPI == 0) {
            g_out2[(size_t)m * Dm + n0 + col] = val;
        } else {
            int b = m >> 12, l = m & 4095;
            size_t rowoff = ((size_t)(b * Hh + h0) * Lq + l) * Ee + col;
            if (sec == 2) {
                g_v[rowoff] = val;
            } else {
                float cum = g_cum[(size_t)(b * Hh + h0) * Lq + l];
                float mul = (sec == 0) ? 0.125f * expf(cum) : expf(-cum);
                float fm = (val > 0.f) ? val + 1.f : expf(val);
                ((sec == 0) ? g_q : g_k)[rowoff] = fm * mul;
            }
        }
    }
}

// ---------------- K2: per-chunk S = KᵀV (64x64), z = Σk ----------------------
__global__ void chunk_sum_kernel() {
    __shared__ float Ks[32][Ee];
    __shared__ float Vs[32][Ee];
    int blk = blockIdx.x;
    int c = blk & (NC - 1);
    int bh = blk >> 5;
    int tid = threadIdx.x;
    int tx = tid & 15, ty = tid >> 4;
    const float* Kb = g_k + ((size_t)bh * Lq + c * CS) * Ee;
    const float* Vb = g_v + ((size_t)bh * Lq + c * CS) * Ee;
    float acc[4][4];
#pragma unroll
    for (int i = 0; i < 4; i++)
#pragma unroll
        for (int j = 0; j < 4; j++) acc[i][j] = 0.f;
    float zacc[4] = {0.f, 0.f, 0.f, 0.f};
    for (int r0 = 0; r0 < CS; r0 += 32) {
#pragma unroll
        for (int u = 0; u < 2; u++) {
            int idx = tid + u * 256;
            ((float4*)Ks)[idx] = ((const float4*)(Kb + r0 * Ee))[idx];
            ((float4*)Vs)[idx] = ((const float4*)(Vb + r0 * Ee))[idx];
        }
        __syncthreads();
#pragma unroll
        for (int r = 0; r < 32; r++) {
            float a[4], bq[4];
#pragma unroll
            for (int i = 0; i < 4; i++) a[i] = Ks[r][ty * 4 + i];
#pragma unroll
            for (int j = 0; j < 4; j++) bq[j] = Vs[r][tx * 4 + j];
#pragma unroll
            for (int i = 0; i < 4; i++) {
                zacc[i] += a[i];
#pragma unroll
                for (int j = 0; j < 4; j++) acc[i][j] += a[i] * bq[j];
            }
        }
        __syncthreads();
    }
    float* Sd = g_S + (size_t)blk * Ee * Ee;
#pragma unroll
    for (int i = 0; i < 4; i++)
#pragma unroll
        for (int j = 0; j < 4; j++) Sd[(ty * 4 + i) * Ee + tx * 4 + j] = acc[i][j];
    if (tx == 0) {
        float* zd = g_z + (size_t)blk * Ee;
#pragma unroll
        for (int i = 0; i < 4; i++) zd[ty * 4 + i] = zacc[i];
    }
}

// ---------------- K3: exclusive prefix over chunks (full-width grid) ---------
__global__ __launch_bounds__(512) void chunk_prefix_kernel() {
    int bh = blockIdx.x;
    int idx = blockIdx.y * 512 + threadIdx.x;
    float* p = g_S + (size_t)bh * NC * (Ee * Ee) + idx;
    float v[NC];
#pragma unroll
    for (int c = 0; c < NC; c++) v[c] = p[(size_t)c * (Ee * Ee)];
    float carry = 0.f;
#pragma unroll
    for (int c = 0; c < NC; c++) { p[(size_t)c * (Ee * Ee)] = carry; carry += v[c]; }
    if (blockIdx.y == 0 && threadIdx.x < Ee) {
        float* pz = g_z + (size_t)bh * NC * Ee + threadIdx.x;
        float zv[NC];
#pragma unroll
        for (int c = 0; c < NC; c++) zv[c] = pz[c * Ee];
        float zc = 0.f;
#pragma unroll
        for (int c = 0; c < NC; c++) { pz[c * Ee] = zc; zc += zv[c]; }
    }
}

// ---------------- K4: chunked causal linear attention (writes bf16 split) ----
__global__ __launch_bounds__(128) void attn_kernel() {
    __shared__ float sh[Ee * Ee + Ee];
    int blk = blockIdx.x;
    int c = blk & 31;
    int bh = blk >> 5;
    int t = threadIdx.x;
    const float* qp = g_q + ((size_t)bh * Lq + c * CS + t) * Ee;
    float q[Ee];
#pragma unroll
    for (int i = 0; i < 16; i++) {
        float4 v4 = ((const float4*)qp)[i];
        q[4 * i] = v4.x; q[4 * i + 1] = v4.y; q[4 * i + 2] = v4.z; q[4 * i + 3] = v4.w;
    }
    const float* Sp = g_S + (size_t)blk * Ee * Ee;
#pragma unroll
    for (int u = 0; u < 8; u++) ((float4*)sh)[t + u * 128] = ((const float4*)Sp)[t + u * 128];
    if (t < 16) ((float4*)(sh + Ee * Ee))[t] = ((const float4*)(g_z + (size_t)blk * Ee))[t];
    __syncthreads();

    float num[Ee];
#pragma unroll
    for (int f = 0; f < Ee; f++) num[f] = 0.f;
    float den = 1e-6f;
#pragma unroll
    for (int e = 0; e < Ee; e++) {
        float qe = q[e];
        den += qe * sh[Ee * Ee + e];
        const float4* srow = (const float4*)(sh + e * Ee);
#pragma unroll
        for (int f4 = 0; f4 < 16; f4++) {
            float4 sv = srow[f4];
            num[4 * f4]     += qe * sv.x;
            num[4 * f4 + 1] += qe * sv.y;
            num[4 * f4 + 2] += qe * sv.z;
            num[4 * f4 + 3] += qe * sv.w;
        }
    }
    __syncthreads();

    const float* Kb = g_k + ((size_t)bh * Lq + c * CS) * Ee;
    const float* Vb = g_v + ((size_t)bh * Lq + c * CS) * Ee;
    for (int s0 = 0; s0 < CS; s0 += 32) {
#pragma unroll
        for (int u = 0; u < 4; u++) {
            int idx = t + u * 128;
            ((float4*)sh)[idx] = ((const float4*)(Kb + s0 * Ee))[idx];
            ((float4*)(sh + 2048))[idx] = ((const float4*)(Vb + s0 * Ee))[idx];
        }
        __syncthreads();
        for (int s = 0; s < 32; s++) {
            if (s0 + s <= t) {
                float a = 0.f;
                const float4* krow = (const float4*)(sh + s * Ee);
#pragma unroll
                for (int e4 = 0; e4 < 16; e4++) {
                    float4 kv = krow[e4];
                    a += q[4 * e4] * kv.x + q[4 * e4 + 1] * kv.y
                       + q[4 * e4 + 2] * kv.z + q[4 * e4 + 3] * kv.w;
                }
                den += a;
                const float4* vrow = (const float4*)(sh + 2048 + s * Ee);
#pragma unroll
                for (int f4 = 0; f4 < 16; f4++) {
                    float4 vv = vrow[f4];
                    num[4 * f4]     += a * vv.x;
                    num[4 * f4 + 1] += a * vv.y;
                    num[4 * f4 + 2] += a * vv.z;
                    num[4 * f4 + 3] += a * vv.w;
                }
            }
        }
        __syncthreads();
    }
    float invd = 1.0f / den;
    int b = bh >> 3, h = bh & 7;
    size_t off = ((size_t)(b * Lq + c * CS + t)) * Dm + h * Ee;
    __nv_bfloat162* oh = (__nv_bfloat162*)(g_ahi + off);
    __nv_bfloat162* ol = (__nv_bfloat162*)(g_alo + off);
#pragma unroll
    for (int f2 = 0; f2 < 32; f2++) {
        float v0 = num[2 * f2] * invd, v1 = num[2 * f2 + 1] * invd;
        __nv_bfloat162 ph, pl;
        split2(v0, v1, ph, pl);
        oh[f2] = ph; ol[f2] = pl;
    }
}

// ---------------- K6: RMSNorm -------------------------------------------------
__global__ void rmsnorm_kernel(const float* __restrict__ scale, float* __restrict__ out) {
    int row = blockIdx.x;
    int tid = threadIdx.x;
    const float* r = g_out2 + (size_t)row * Dm;
    float v0 = r[tid], v1 = r[tid + 256];
    float ss = v0 * v0 + v1 * v1;
#pragma unroll
    for (int o = 16; o; o >>= 1) ss += __shfl_xor_sync(0xffffffffu, ss, o);
    __shared__ float wsum[8];
    __shared__ float rn_s;
    if ((tid & 31) == 0) wsum[tid >> 5] = ss;
    __syncthreads();
    if (tid == 0) {
        float tt = 0.f;
#pragma unroll
        for (int i = 0; i < 8; i++) tt += wsum[i];
        rn_s = rsqrtf(tt * (1.0f / 512.0f) + 1e-8f);
    }
    __syncthreads();
    float rn = rn_s;
    out[(size_t)row * Dm + tid] = v0 * rn * scale[tid];
    out[(size_t)row * Dm + tid + 256] = v1 * rn * scale[tid + 256];
}

// ---------------- launch ------------------------------------------------------
extern "C" void kernel_launch(void* const* d_in, const int* in_sizes, int n_in,
                              void* d_out, int out_size) {
    const float* x          = (const float*)d_in[0];
    const float* qkv_w      = (const float*)d_in[1];
    const float* qkv_b      = (const float*)d_in[2];
    const float* out_w      = (const float*)d_in[3];
    const float* out_b      = (const float*)d_in[4];
    const float* decay_w    = (const float*)d_in[5];
    const float* decay_b    = (const float*)d_in[6];
    const float* norm_scale = (const float*)d_in[7];
    float* out = (float*)d_out;
    (void)in_sizes; (void)n_in; (void)out_size;

    // dynamic smem: max(3 stages x 24 KB = 73728, C staging 34816)
    const int DYN = 73728;
    static bool attr_set = false;
    if (!attr_set) {
        cudaFuncSetAttribute(gemm_mma_kernel<1>, cudaFuncAttributeMaxDynamicSharedMemorySize, DYN);
        cudaFuncSetAttribute(gemm_mma_kernel<0>, cudaFuncAttributeMaxDynamicSharedMemorySize, DYN);
        attr_set = true;
    }

    split_w_kernel<<<1024, 256>>>(qkv_w, out_w);
    split_x_decay_kernel<<<1024, 256>>>(x, decay_w, decay_b);
    cum_scan_kernel<<<BHn, 512>>>();

    gemm_mma_kernel<1><<<dim3(24, 64), 256, DYN>>>(qkv_b);

    chunk_sum_kernel<<<BHn * NC, 256>>>();
    chunk_prefix_kernel<<<dim3(BHn, 8), 512>>>();
    attn_kernel<<<BHn * NC, 128>>>();

    gemm_mma_kernel<0><<<dim3(8, 64), 256, DYN>>>(out_b);

    rmsnorm_kernel<<<Bsz * Lq, 256>>>(norm_scale, out);
}